// round 9
// baseline (speedup 1.0000x reference)
#include <cuda_runtime.h>
#include <cstdint>

#define NQ 65536
#define NC 2048
#define AS 132   // activation smem row stride (floats)
#define WS 144   // weight-tile smem row stride (floats)

typedef unsigned long long ull;

// ------- device scratch (static __device__ globals: allocation-free) -------
__device__ float g_X[NQ * 128];    // [query_codes 64 | xyz_emb 63 | 0]
__device__ float g_DIR[NQ * 32];   // [dir_emb 27 | 0 x5]
__device__ float g_U[NQ * 128];    // X @ W2x   (skip-path partial)
__device__ float g_V[NQ * 64];     // dir @ Wd_dir + bd
__device__ int   g_hist[4096];
__device__ int   g_offs[4096];
__device__ int   g_perm[NQ];
__device__ float4 g_cps[NC];       // codes sorted by Morton cell: {x,y,z,||c||^2}
__device__ int    g_cmap[NC];      // sorted index -> original code index
__device__ float4 g_chunk[64];     // per-32-code chunk: {bbox center, radius}
__device__ int    g_chunkcell[64]; // Morton cell of chunk head
__device__ float g_W0p[128 * 128];
__device__ float g_W2xp[128 * 128];
__device__ float g_W2hp[128 * 128];
__device__ float g_Wdfp[128 * 64];

// ------------------------- f32x2 helpers -----------------------------------
__device__ __forceinline__ ull pk2(float lo, float hi) {
    ull r; asm("mov.b64 %0,{%1,%2};" : "=l"(r) : "f"(lo), "f"(hi)); return r;
}
__device__ __forceinline__ void fma2(ull& c, ull a, ull b) {
    asm("fma.rn.f32x2 %0,%1,%2,%0;" : "+l"(c) : "l"(a), "l"(b));
}
__device__ __forceinline__ float2 up2(ull v) {
    float2 r; asm("mov.b64 {%0,%1},%2;" : "=f"(r.x), "=f"(r.y) : "l"(v)); return r;
}
__device__ __forceinline__ int wsw(int col) {
    int g = col >> 3;
    return g * 8 + (g >> 2) * 4 + (col & 7);
}
// 12-bit Morton cell on a 16^3 grid
__device__ __forceinline__ int morton16(float x, float y, float z) {
    int ix = min(15, max(0, (int)(x * 16.f)));
    int iy = min(15, max(0, (int)(y * 16.f)));
    int iz = min(15, max(0, (int)(z * 16.f)));
    int m = 0;
#pragma unroll
    for (int b = 0; b < 4; b++)
        m |= (((ix >> b) & 1) << (3 * b + 2)) | (((iy >> b) & 1) << (3 * b + 1))
           | (((iz >> b) & 1) << (3 * b));
    return m;
}

// --------------------- spatial counting sort of queries --------------------
__global__ void zero_hist() { g_hist[blockIdx.x * 256 + threadIdx.x] = 0; }

__global__ void hist_k(const float* __restrict__ qp) {
    int q = blockIdx.x * 256 + threadIdx.x;
    atomicAdd(&g_hist[morton16(qp[3 * q], qp[3 * q + 1], qp[3 * q + 2])], 1);
}

__global__ void __launch_bounds__(1024) scan_k() {   // 1 block
    __shared__ int s[1024];
    int tid = threadIdx.x;
    int v[4]; int sum = 0;
#pragma unroll
    for (int i = 0; i < 4; i++) { v[i] = g_hist[tid * 4 + i]; sum += v[i]; }
    s[tid] = sum; __syncthreads();
    for (int off = 1; off < 1024; off <<= 1) {
        int t = (tid >= off) ? s[tid - off] : 0;
        __syncthreads();
        s[tid] += t;
        __syncthreads();
    }
    int run = tid ? s[tid - 1] : 0;
#pragma unroll
    for (int i = 0; i < 4; i++) { g_offs[tid * 4 + i] = run; run += v[i]; }
}

__global__ void scatter_k(const float* __restrict__ qp) {
    int q = blockIdx.x * 256 + threadIdx.x;
    int cell = morton16(qp[3 * q], qp[3 * q + 1], qp[3 * q + 2]);
    int pos = atomicAdd(&g_offs[cell], 1);
    g_perm[pos] = q;
}

// -------- sort code positions by Morton cell (deterministic bitonic) -------
__global__ void __launch_bounds__(256) sort_codes(const int* __restrict__ indices,
                                                  const float* __restrict__ cpos) {
    __shared__ unsigned key[NC];   // (cell << 11) | original index
    int tid = threadIdx.x;
    int ib = indices[0];
    const float* cp = cpos + (size_t)ib * NC * 3;
    for (int i = tid; i < NC; i += 256) {
        int cell = morton16(cp[3 * i], cp[3 * i + 1], cp[3 * i + 2]);
        key[i] = ((unsigned)cell << 11) | (unsigned)i;
    }
    __syncthreads();
    for (int k = 2; k <= NC; k <<= 1) {
        for (int j = k >> 1; j > 0; j >>= 1) {
            for (int t = tid; t < NC; t += 256) {
                int p = t ^ j;
                if (p > t) {
                    bool up = ((t & k) == 0);
                    unsigned a = key[t], b = key[p];
                    if ((a > b) == up) { key[t] = b; key[p] = a; }
                }
            }
            __syncthreads();
        }
    }
    for (int i = tid; i < NC; i += 256) {
        int c = key[i] & 0x7FF;
        float x = cp[3 * c], y = cp[3 * c + 1], z = cp[3 * c + 2];
        g_cps[i] = make_float4(x, y, z, fmaf(x, x, fmaf(y, y, z * z)));
        g_cmap[i] = c;
    }
    __syncthreads();
    if (tid < 64) {
        float mnx = 1e30f, mny = 1e30f, mnz = 1e30f;
        float mxx = -1e30f, mxy = -1e30f, mxz = -1e30f;
        for (int s = 0; s < 32; s++) {
            int c = key[tid * 32 + s] & 0x7FF;
            float x = cp[3 * c], y = cp[3 * c + 1], z = cp[3 * c + 2];
            mnx = fminf(mnx, x); mny = fminf(mny, y); mnz = fminf(mnz, z);
            mxx = fmaxf(mxx, x); mxy = fmaxf(mxy, y); mxz = fmaxf(mxz, z);
        }
        float cx = 0.5f * (mnx + mxx), cy = 0.5f * (mny + mxy), cz = 0.5f * (mnz + mxz);
        float hx = 0.5f * (mxx - mnx), hy = 0.5f * (mxy - mny), hz = 0.5f * (mxz - mnz);
        float rad = sqrtf(fmaf(hx, hx, fmaf(hy, hy, hz * hz))) + 1e-4f;
        g_chunk[tid] = make_float4(cx, cy, cz, rad);
        g_chunkcell[tid] = (int)(key[tid * 32] >> 11);
    }
}

// ------------------------- weight prep -------------------------------------
__global__ void prep_weights(const float* __restrict__ W0,
                             const float* __restrict__ W2,
                             const float* __restrict__ Wd) {
    const int T0 = 16384, T1 = 16384, T2 = 16384, T3 = 8192;
    int total = T0 + T1 + T2 + T3;
    for (int i = blockIdx.x * blockDim.x + threadIdx.x; i < total;
         i += gridDim.x * blockDim.x) {
        if (i < T0) {
            int r = i >> 7, c = i & 127;
            g_W0p[i] = (r < 127) ? W0[r * 128 + c] : 0.f;
        } else if (i < T0 + T1) {
            int j = i - T0; int r = j >> 7, c = j & 127;
            g_W2xp[j] = (r < 127) ? W2[r * 128 + c] : 0.f;
        } else if (i < T0 + T1 + T2) {
            int j = i - T0 - T1; int r = j >> 7, c = j & 127;
            g_W2hp[j] = W2[(127 + r) * 128 + c];
        } else {
            int j = i - T0 - T1 - T2;
            g_Wdfp[j] = Wd[j];
        }
    }
}

// --------------------- pack xyz / dir embeddings ---------------------------
__global__ void pack_inputs(const float* __restrict__ xyzdir) {
    const int TA = NQ * 64;
    const int total = NQ * 64 + NQ * 32;
    for (int i = blockIdx.x * blockDim.x + threadIdx.x; i < total;
         i += gridDim.x * blockDim.x) {
        if (i < TA) {
            int q = i >> 6, e = i & 63;
            g_X[q * 128 + 64 + e] = (e < 63) ? xyzdir[q * 90 + e] : 0.f;
        } else {
            int j = i - TA; int q = j >> 5, e = j & 31;
            g_DIR[j] = (e < 27) ? xyzdir[q * 90 + 63 + e] : 0.f;
        }
    }
}

// ---------------- V = dir @ Wd[128:155] + bd  ------------------------------
__global__ void __launch_bounds__(256) vcomp(const float* __restrict__ Wd,
                                             const float* __restrict__ bd) {
    __shared__ float sw[27 * 64];
    __shared__ float sb[64];
    int tid = threadIdx.x;
    for (int i = tid; i < 27 * 64; i += 256) sw[i] = Wd[128 * 64 + i];
    if (tid < 64) sb[tid] = bd[tid];
    __syncthreads();
    int idx = blockIdx.x * 256 + tid;
    int q = idx >> 4, c0 = (idx & 15) * 4;
    float a0 = sb[c0], a1 = sb[c0 + 1], a2 = sb[c0 + 2], a3 = sb[c0 + 3];
#pragma unroll
    for (int k = 0; k < 27; k++) {
        float dv = g_DIR[q * 32 + k];
        a0 = fmaf(dv, sw[k * 64 + c0 + 0], a0);
        a1 = fmaf(dv, sw[k * 64 + c0 + 1], a1);
        a2 = fmaf(dv, sw[k * 64 + c0 + 2], a2);
        a3 = fmaf(dv, sw[k * 64 + c0 + 3], a3);
    }
    *reinterpret_cast<float4*>(g_V + (size_t)q * 64 + c0) = make_float4(a0, a1, a2, a3);
}

// --- KNN(16) + interp: Morton-clustered queries, chunk-skip pruned scan ----
__global__ void __launch_bounds__(128) knn_interp(const int* __restrict__ indices,
                                                  const float* __restrict__ qp,
                                                  const float* __restrict__ codes) {
    __shared__ float4 sp[NC];      // sorted {x, y, z, ||c||^2}
    __shared__ float4 sck[64];     // chunk {center, radius}
    __shared__ int    scc[64];     // chunk head cell
    __shared__ int    smap[NC];    // sorted -> original
    __shared__ float s_w[128 * 16];
    __shared__ int   s_i[128 * 16];
    __shared__ int   s_q[128];
    int tid = threadIdx.x;
    int ib = indices[0];
    const float* cc = codes + (size_t)ib * NC * 64;
    for (int i = tid; i < NC; i += 128) { sp[i] = g_cps[i]; smap[i] = g_cmap[i]; }
    if (tid < 64) { sck[tid] = g_chunk[tid]; scc[tid] = g_chunkcell[tid]; }
    __syncthreads();

    int q = g_perm[blockIdx.x * 128 + tid];
    float qx = qp[q * 3 + 0], qy = qp[q * 3 + 1], qz = qp[q * 3 + 2];
    float qx2 = -2.f * qx, qy2 = -2.f * qy, qz2 = -2.f * qz;
    float q2 = fmaf(qx, qx, fmaf(qy, qy, qz * qz));

    // warp-uniform start chunk: nearest chunk by Morton cell of lane 0
    int mycell = morton16(qx, qy, qz);
    int lo = 0, hi = 63;
    while (lo < hi) {
        int mid = (lo + hi + 1) >> 1;
        if (scc[mid] <= mycell) lo = mid; else hi = mid - 1;
    }
    int startc = __shfl_sync(0xFFFFFFFFu, lo, 0);

    unsigned bk[16];
#pragma unroll
    for (int j = 0; j < 16; j++) bk[j] = 0x7F7FFFFFu;
    float bnd = __uint_as_float(0x7F7FF800u) - q2;
    float rbnd = 1e30f;

    for (int jj = 0; jj < 64; jj++) {
        int ch = startc + jj; if (ch >= 64) ch -= 64;
        float4 cm = sck[ch];
        float ddx = qx - cm.x, ddy = qy - cm.y, ddz = qz - cm.z;
        float dc2 = fmaf(ddx, ddx, fmaf(ddy, ddy, ddz * ddz));
        float thr = rbnd + cm.w;
        bool need = dc2 < thr * thr;
        if (!__any_sync(0xFFFFFFFFu, need)) continue;
        int base = ch << 5;
#pragma unroll 4
        for (int c = 0; c < 32; c++) {
            float4 v = sp[base + c];
            float dp = fmaf(v.x, qx2, fmaf(v.y, qy2, fmaf(v.z, qz2, v.w)));
            if (dp < bnd) {
                float dfull = fmaxf(dp + q2, 0.f);
                unsigned cur = (__float_as_uint(dfull) & 0xFFFFF800u)
                             | (unsigned)(base + c);
#pragma unroll
                for (int j = 0; j < 16; j++) {
                    unsigned mn = min(bk[j], cur);
                    unsigned mx = max(bk[j], cur);
                    bk[j] = mn; cur = mx;
                }
                float d15 = __uint_as_float(bk[15] & 0xFFFFF800u);
                bnd = d15 - q2;
                rbnd = __fsqrt_ru(d15);
            }
        }
    }

    // exact distances -> normalized 1/d2 weights (original indices for gather)
    float w[16]; int ci[16]; float wsum = 0.f;
#pragma unroll
    for (int k = 0; k < 16; k++) {
        int cs = (int)(bk[k] & 0x7FFu);
        ci[k] = smap[cs];
        float4 v = sp[cs];
        float dx = qx - v.x, dy = qy - v.y, dz = qz - v.z;
        float d2 = fmaf(dx, dx, fmaf(dy, dy, dz * dz)) + 1e-16f;
        w[k] = 1.0f / d2; wsum += w[k];
    }
    float inv = 1.0f / wsum;
#pragma unroll
    for (int k = 0; k < 16; k++) {
        s_w[tid * 16 + k] = w[k] * inv;
        s_i[tid * 16 + k] = ci[k];
    }
    s_q[tid] = q;
    __syncwarp();

    // warp-cooperative gather: lanes cover 64 code dims, coalesced rows
    int lane = tid & 31;
    int wbase2 = tid & ~31;
    for (int s = 0; s < 32; s++) {
        int t = wbase2 + s;
        int qq = s_q[t];
        float a0 = 0.f, a1 = 0.f;
#pragma unroll
        for (int k = 0; k < 16; k++) {
            int cix = s_i[t * 16 + k];
            float wk = s_w[t * 16 + k];
            const float* row = cc + cix * 64;
            a0 = fmaf(wk, row[lane], a0);
            a1 = fmaf(wk, row[lane + 32], a1);
        }
        g_X[(size_t)qq * 128 + lane] = a0;
        g_X[(size_t)qq * 128 + 32 + lane] = a1;
    }
}

// ===================== fused MLP (entire network) ==========================
#define SMEM_FLOATS (128 * AS + 2 * 32 * WS + 128 + 192)

__global__ void __launch_bounds__(256, 2) fused_mlp(
    const float* __restrict__ W1, const float* __restrict__ W3,
    const float* __restrict__ Wf,
    const float* __restrict__ b0, const float* __restrict__ b1,
    const float* __restrict__ b2, const float* __restrict__ b3,
    const float* __restrict__ bf,
    const float* __restrict__ Wsig, const float* __restrict__ bs,
    const float* __restrict__ Wr,   const float* __restrict__ br,
    float* __restrict__ out)
{
    extern __shared__ float sm[];
    float* A   = sm;
    float* Wb  = sm + 128 * AS;
    float* wsv = Wb + 2 * 32 * WS;
    float* wrv = wsv + 128;

    int tid = threadIdx.x;
    int tx = tid & 15, ty = tid >> 4;
    int rowBlk = blockIdx.x * 128;
    const int wbase = tx * 8 + (tx >> 2) * 4;

    if (tid < 128) wsv[tid] = Wsig[tid];
    if (tid < 192) wrv[tid] = Wr[tid];

    {
        const float4* src = reinterpret_cast<const float4*>(g_X + (size_t)rowBlk * 128);
#pragma unroll
        for (int i = 0; i < 16; i++) {
            int f4 = tid + i * 256;
            float4 v = src[f4];
            int row = f4 >> 5, c4 = f4 & 31;
            *reinterpret_cast<float4*>(A + row * AS + c4 * 4) = v;
        }
    }

    const float* Wgs[6] = { g_W2xp, g_W0p, W1, g_W2hp, W3, Wf };
    const float* bgs[6] = { b0, b0, b1, b2, b3, bf };

    float sigR = 0.f;
    ull acc[8][4];

    for (int L = 0; L < 6; ++L) {
        const float* Wg = Wgs[L];
#pragma unroll
        for (int i = 0; i < 8; i++)
#pragma unroll
            for (int j = 0; j < 4; j++) acc[i][j] = 0ULL;

#pragma unroll
        for (int i = 0; i < 4; i++) {
            float4 v = reinterpret_cast<const float4*>(Wg)[tid * 4 + i];
            int flat = tid * 16 + i * 4;
            int k = flat >> 7, col = flat & 127;
            *reinterpret_cast<float4*>(Wb + k * WS + wsw(col)) = v;
        }
        __syncthreads();

        for (int t = 0; t < 4; t++) {
            float4 pf[4];
            if (t < 3) {
                const float4* g = reinterpret_cast<const float4*>(Wg + (t + 1) * 4096);
#pragma unroll
                for (int i = 0; i < 4; i++) pf[i] = g[tid * 4 + i];
            }
            const float* Wt = Wb + (t & 1) * (32 * WS);
#pragma unroll
            for (int k4 = 0; k4 < 8; k4++) {
                ulonglong2 wq0[4], wq1[4];
#pragma unroll
                for (int kk = 0; kk < 4; kk++) {
                    const float* wp = Wt + (k4 * 4 + kk) * WS + wbase;
                    wq0[kk] = *reinterpret_cast<const ulonglong2*>(wp);
                    wq1[kk] = *reinterpret_cast<const ulonglong2*>(wp + 4);
                }
#pragma unroll
                for (int r4 = 0; r4 < 2; r4++) {
                    float4 ar[4];
#pragma unroll
                    for (int r = 0; r < 4; r++)
                        ar[r] = *reinterpret_cast<const float4*>(
                            A + (ty * 8 + r4 * 4 + r) * AS + t * 32 + k4 * 4);
#pragma unroll
                    for (int kk = 0; kk < 4; kk++) {
#pragma unroll
                        for (int r = 0; r < 4; r++) {
                            float av = (kk == 0) ? ar[r].x : (kk == 1) ? ar[r].y
                                     : (kk == 2) ? ar[r].z : ar[r].w;
                            ull ad = pk2(av, av);
                            int ri = r4 * 4 + r;
                            fma2(acc[ri][0], ad, wq0[kk].x);
                            fma2(acc[ri][1], ad, wq0[kk].y);
                            fma2(acc[ri][2], ad, wq1[kk].x);
                            fma2(acc[ri][3], ad, wq1[kk].y);
                        }
                    }
                }
            }
            if (t < 3) {
                float* d = Wb + ((t + 1) & 1) * (32 * WS);
#pragma unroll
                for (int i = 0; i < 4; i++) {
                    int flat = tid * 16 + i * 4;
                    int k = flat >> 7, col = flat & 127;
                    *reinterpret_cast<float4*>(d + k * WS + wsw(col)) = pf[i];
                }
            }
            __syncthreads();
        }

        if (L == 0) {
#pragma unroll
            for (int i = 0; i < 8; i++) {
                size_t row = (size_t)(rowBlk + ty * 8 + i);
                float o[8];
#pragma unroll
                for (int j = 0; j < 4; j++) {
                    float2 v = up2(acc[i][j]); o[2 * j] = v.x; o[2 * j + 1] = v.y;
                }
                *reinterpret_cast<float4*>(g_U + row * 128 + tx * 8) =
                    make_float4(o[0], o[1], o[2], o[3]);
                *reinterpret_cast<float4*>(g_U + row * 128 + tx * 8 + 4) =
                    make_float4(o[4], o[5], o[6], o[7]);
            }
        } else {
            const float* bg = bgs[L];
            float4 bA = *reinterpret_cast<const float4*>(bg + tx * 8);
            float4 bB = *reinterpret_cast<const float4*>(bg + tx * 8 + 4);
            bool relu = (L != 5);
#pragma unroll
            for (int i = 0; i < 8; i++) {
                int row = ty * 8 + i;
                float o[8];
#pragma unroll
                for (int j = 0; j < 4; j++) {
                    float2 v = up2(acc[i][j]); o[2 * j] = v.x; o[2 * j + 1] = v.y;
                }
                if (L == 3) {
                    size_t gr = (size_t)(rowBlk + row);
                    float4 u0 = *reinterpret_cast<const float4*>(g_U + gr * 128 + tx * 8);
                    float4 u1 = *reinterpret_cast<const float4*>(g_U + gr * 128 + tx * 8 + 4);
                    o[0] += u0.x; o[1] += u0.y; o[2] += u0.z; o[3] += u0.w;
                    o[4] += u1.x; o[5] += u1.y; o[6] += u1.z; o[7] += u1.w;
                }
                o[0] += bA.x; o[1] += bA.y; o[2] += bA.z; o[3] += bA.w;
                o[4] += bB.x; o[5] += bB.y; o[6] += bB.z; o[7] += bB.w;
                if (relu) {
#pragma unroll
                    for (int c = 0; c < 8; c++) o[c] = fmaxf(o[c], 0.f);
                }
                *reinterpret_cast<float4*>(A + row * AS + tx * 8) =
                    make_float4(o[0], o[1], o[2], o[3]);
                *reinterpret_cast<float4*>(A + row * AS + tx * 8 + 4) =
                    make_float4(o[4], o[5], o[6], o[7]);
            }
        }
        __syncthreads();

        if (L == 4 && tid < 128) {
            float s = 0.f;
#pragma unroll
            for (int k4 = 0; k4 < 32; k4++) {
                float4 hv = *reinterpret_cast<const float4*>(A + tid * AS + k4 * 4);
                s = fmaf(hv.x, wsv[k4 * 4 + 0], s);
                s = fmaf(hv.y, wsv[k4 * 4 + 1], s);
                s = fmaf(hv.z, wsv[k4 * 4 + 2], s);
                s = fmaf(hv.w, wsv[k4 * 4 + 3], s);
            }
            sigR = s + bs[0];
        }
    }

    // ---- dir layer ----
    int tx8 = tid & 7, ty32 = tid >> 3;
    const int wb64 = tx8 * 8 + (tx8 >> 2) * 4;
    ull acc2[4][4];
#pragma unroll
    for (int i = 0; i < 4; i++)
#pragma unroll
        for (int j = 0; j < 4; j++) acc2[i][j] = 0ULL;

#pragma unroll
    for (int i = 0; i < 2; i++) {
        float4 v = reinterpret_cast<const float4*>(g_Wdfp)[tid * 2 + i];
        int flat = tid * 8 + i * 4;
        int k = flat >> 6, col = flat & 63;
        *reinterpret_cast<float4*>(Wb + k * WS + wsw(col)) = v;
    }
    __syncthreads();

    for (int t = 0; t < 4; t++) {
        float4 pf[2];
        if (t < 3) {
            const float4* g = reinterpret_cast<const float4*>(g_Wdfp + (t + 1) * 2048);
#pragma unroll
            for (int i = 0; i < 2; i++) pf[i] = g[tid * 2 + i];
        }
        const float* Wt = Wb + (t & 1) * (32 * WS);
#pragma unroll
        for (int k4 = 0; k4 < 8; k4++) {
            ulonglong2 wq0[4], wq1[4];
#pragma unroll
            for (int kk = 0; kk < 4; kk++) {
                const float* wp = Wt + (k4 * 4 + kk) * WS + wb64;
                wq0[kk] = *reinterpret_cast<const ulonglong2*>(wp);
                wq1[kk] = *reinterpret_cast<const ulonglong2*>(wp + 4);
            }
            float4 ar[4];
#pragma unroll
            for (int r = 0; r < 4; r++)
                ar[r] = *reinterpret_cast<const float4*>(
                    A + (ty32 * 4 + r) * AS + t * 32 + k4 * 4);
#pragma unroll
            for (int kk = 0; kk < 4; kk++) {
#pragma unroll
                for (int r = 0; r < 4; r++) {
                    float av = (kk == 0) ? ar[r].x : (kk == 1) ? ar[r].y
                             : (kk == 2) ? ar[r].z : ar[r].w;
                    ull ad = pk2(av, av);
                    fma2(acc2[r][0], ad, wq0[kk].x);
                    fma2(acc2[r][1], ad, wq0[kk].y);
                    fma2(acc2[r][2], ad, wq1[kk].x);
                    fma2(acc2[r][3], ad, wq1[kk].y);
                }
            }
        }
        if (t < 3) {
            float* d = Wb + ((t + 1) & 1) * (32 * WS);
#pragma unroll
            for (int i = 0; i < 2; i++) {
                int flat = tid * 8 + i * 4;
                int k = flat >> 6, col = flat & 63;
                *reinterpret_cast<float4*>(d + k * WS + wsw(col)) = pf[i];
            }
        }
        __syncthreads();
    }

#pragma unroll
    for (int r = 0; r < 4; r++) {
        int row = ty32 * 4 + r;
        size_t gr = (size_t)(rowBlk + row);
        float4 v0 = *reinterpret_cast<const float4*>(g_V + gr * 64 + tx8 * 8);
        float4 v1 = *reinterpret_cast<const float4*>(g_V + gr * 64 + tx8 * 8 + 4);
        float o[8];
#pragma unroll
        for (int j = 0; j < 4; j++) {
            float2 v = up2(acc2[r][j]); o[2 * j] = v.x; o[2 * j + 1] = v.y;
        }
        o[0] += v0.x; o[1] += v0.y; o[2] += v0.z; o[3] += v0.w;
        o[4] += v1.x; o[5] += v1.y; o[6] += v1.z; o[7] += v1.w;
#pragma unroll
        for (int c = 0; c < 8; c++) o[c] = fmaxf(o[c], 0.f);
        *reinterpret_cast<float4*>(A + row * AS + tx8 * 8) =
            make_float4(o[0], o[1], o[2], o[3]);
        *reinterpret_cast<float4*>(A + row * AS + tx8 * 8 + 4) =
            make_float4(o[4], o[5], o[6], o[7]);
    }
    __syncthreads();

    if (tid < 128) {
        float r0 = br[0], r1 = br[1], r2 = br[2];
#pragma unroll
        for (int k4 = 0; k4 < 16; k4++) {
            float4 dv = *reinterpret_cast<const float4*>(A + tid * AS + k4 * 4);
            const float* wr0 = wrv + k4 * 12;
            r0 = fmaf(dv.x, wr0[0], r0); r1 = fmaf(dv.x, wr0[1], r1); r2 = fmaf(dv.x, wr0[2], r2);
            r0 = fmaf(dv.y, wr0[3], r0); r1 = fmaf(dv.y, wr0[4], r1); r2 = fmaf(dv.y, wr0[5], r2);
            r0 = fmaf(dv.z, wr0[6], r0); r1 = fmaf(dv.z, wr0[7], r1); r2 = fmaf(dv.z, wr0[8], r2);
            r0 = fmaf(dv.w, wr0[9], r0); r1 = fmaf(dv.w, wr0[10], r1); r2 = fmaf(dv.w, wr0[11], r2);
        }
        *reinterpret_cast<float4*>(out + (size_t)(rowBlk + tid) * 4) =
            make_float4(r0, r1, r2, sigR);
    }
}

// ---------------------------------------------------------------------------
extern "C" void kernel_launch(void* const* d_in, const int* in_sizes, int n_in,
                              void* d_out, int out_size) {
    const int*   indices = (const int*)  d_in[0];
    const float* qp      = (const float*)d_in[1];
    const float* xyzdir  = (const float*)d_in[2];
    const float* cpos    = (const float*)d_in[3];
    const float* codes   = (const float*)d_in[4];
    const float* W0 = (const float*)d_in[5],  *b0 = (const float*)d_in[6];
    const float* W1 = (const float*)d_in[7],  *b1 = (const float*)d_in[8];
    const float* W2 = (const float*)d_in[9],  *b2 = (const float*)d_in[10];
    const float* W3 = (const float*)d_in[11], *b3 = (const float*)d_in[12];
    const float* Wf = (const float*)d_in[13], *bf = (const float*)d_in[14];
    const float* Wd = (const float*)d_in[15], *bd = (const float*)d_in[16];
    const float* Ws = (const float*)d_in[17], *bs = (const float*)d_in[18];
    const float* Wr = (const float*)d_in[19], *br = (const float*)d_in[20];
    float* out = (float*)d_out;

    const int smemBytes = SMEM_FLOATS * 4;
    cudaFuncSetAttribute(fused_mlp, cudaFuncAttributeMaxDynamicSharedMemorySize,
                         smemBytes);

    zero_hist<<<16, 256>>>();
    hist_k<<<NQ / 256, 256>>>(qp);
    scan_k<<<1, 1024>>>();
    scatter_k<<<NQ / 256, 256>>>(qp);
    sort_codes<<<1, 256>>>(indices, cpos);
    prep_weights<<<224, 256>>>(W0, W2, Wd);
    pack_inputs<<<1024, 256>>>(xyzdir);
    vcomp<<<NQ * 16 / 256, 256>>>(Wd, bd);
    knn_interp<<<NQ / 128, 128>>>(indices, qp, codes);
    fused_mlp<<<NQ / 128, 256, smemBytes>>>(W1, W3, Wf, b0, b1, b2, b3, bf,
                                            Ws, bs, Wr, br, out);
}

// round 10
// speedup vs baseline: 1.0172x; 1.0172x over previous
#include <cuda_runtime.h>
#include <cstdint>

#define NQ 65536
#define NC 2048
#define AS 132   // activation smem row stride (floats)
#define WS 144   // weight-tile smem row stride (floats)

typedef unsigned long long ull;

// ------- device scratch (static __device__ globals: allocation-free) -------
__device__ float g_X[NQ * 128];    // [query_codes 64 | xyz_emb 63 | 0]
__device__ float g_DIR[NQ * 32];   // [dir_emb 27 | 0 x5]
__device__ float g_U[NQ * 128];    // X @ W2x   (skip-path partial)
__device__ float g_V[NQ * 64];     // dir @ Wd_dir + bd
__device__ int   g_hist[4096];
__device__ int   g_offs[4096];
__device__ int   g_perm[NQ];
__device__ float g_W0p[128 * 128];
__device__ float g_W2xp[128 * 128];
__device__ float g_W2hp[128 * 128];
__device__ float g_Wdfp[128 * 64];

// ------------------------- f32x2 helpers -----------------------------------
__device__ __forceinline__ ull pk2(float lo, float hi) {
    ull r; asm("mov.b64 %0,{%1,%2};" : "=l"(r) : "f"(lo), "f"(hi)); return r;
}
__device__ __forceinline__ void fma2(ull& c, ull a, ull b) {
    asm("fma.rn.f32x2 %0,%1,%2,%0;" : "+l"(c) : "l"(a), "l"(b));
}
__device__ __forceinline__ float2 up2(ull v) {
    float2 r; asm("mov.b64 {%0,%1},%2;" : "=f"(r.x), "=f"(r.y) : "l"(v)); return r;
}
__device__ __forceinline__ int wsw(int col) {
    int g = col >> 3;
    return g * 8 + (g >> 2) * 4 + (col & 7);
}
__device__ __forceinline__ int cell_of(float x, float y, float z) {
    int ix = min(15, max(0, (int)(x * 16.f)));
    int iy = min(15, max(0, (int)(y * 16.f)));
    int iz = min(15, max(0, (int)(z * 16.f)));
    return (ix << 8) | (iy << 4) | iz;
}

// --------------------- spatial counting sort of queries --------------------
__global__ void zero_hist() { g_hist[blockIdx.x * 256 + threadIdx.x] = 0; }

__global__ void hist_k(const float* __restrict__ qp) {
    int q = blockIdx.x * 256 + threadIdx.x;
    atomicAdd(&g_hist[cell_of(qp[3 * q], qp[3 * q + 1], qp[3 * q + 2])], 1);
}

__global__ void __launch_bounds__(1024) scan_k() {   // 1 block
    __shared__ int s[1024];
    int tid = threadIdx.x;
    int v[4]; int sum = 0;
#pragma unroll
    for (int i = 0; i < 4; i++) { v[i] = g_hist[tid * 4 + i]; sum += v[i]; }
    s[tid] = sum; __syncthreads();
    for (int off = 1; off < 1024; off <<= 1) {
        int t = (tid >= off) ? s[tid - off] : 0;
        __syncthreads();
        s[tid] += t;
        __syncthreads();
    }
    int run = tid ? s[tid - 1] : 0;
#pragma unroll
    for (int i = 0; i < 4; i++) { g_offs[tid * 4 + i] = run; run += v[i]; }
}

__global__ void scatter_k(const float* __restrict__ qp) {
    int q = blockIdx.x * 256 + threadIdx.x;
    int cell = cell_of(qp[3 * q], qp[3 * q + 1], qp[3 * q + 2]);
    int pos = atomicAdd(&g_offs[cell], 1);
    g_perm[pos] = q;
}

// ------------------------- weight prep -------------------------------------
__global__ void prep_weights(const float* __restrict__ W0,
                             const float* __restrict__ W2,
                             const float* __restrict__ Wd) {
    const int T0 = 16384, T1 = 16384, T2 = 16384, T3 = 8192;
    int total = T0 + T1 + T2 + T3;
    for (int i = blockIdx.x * blockDim.x + threadIdx.x; i < total;
         i += gridDim.x * blockDim.x) {
        if (i < T0) {
            int r = i >> 7, c = i & 127;
            g_W0p[i] = (r < 127) ? W0[r * 128 + c] : 0.f;
        } else if (i < T0 + T1) {
            int j = i - T0; int r = j >> 7, c = j & 127;
            g_W2xp[j] = (r < 127) ? W2[r * 128 + c] : 0.f;
        } else if (i < T0 + T1 + T2) {
            int j = i - T0 - T1; int r = j >> 7, c = j & 127;
            g_W2hp[j] = W2[(127 + r) * 128 + c];
        } else {
            int j = i - T0 - T1 - T2;
            g_Wdfp[j] = Wd[j];
        }
    }
}

// --------------------- pack xyz / dir embeddings ---------------------------
__global__ void pack_inputs(const float* __restrict__ xyzdir) {
    const int TA = NQ * 64;
    const int total = NQ * 64 + NQ * 32;
    for (int i = blockIdx.x * blockDim.x + threadIdx.x; i < total;
         i += gridDim.x * blockDim.x) {
        if (i < TA) {
            int q = i >> 6, e = i & 63;
            g_X[q * 128 + 64 + e] = (e < 63) ? xyzdir[q * 90 + e] : 0.f;
        } else {
            int j = i - TA; int q = j >> 5, e = j & 31;
            g_DIR[j] = (e < 27) ? xyzdir[q * 90 + 63 + e] : 0.f;
        }
    }
}

// ---------------- V = dir @ Wd[128:155] + bd  ------------------------------
__global__ void __launch_bounds__(256) vcomp(const float* __restrict__ Wd,
                                             const float* __restrict__ bd) {
    __shared__ float sw[27 * 64];
    __shared__ float sb[64];
    int tid = threadIdx.x;
    for (int i = tid; i < 27 * 64; i += 256) sw[i] = Wd[128 * 64 + i];
    if (tid < 64) sb[tid] = bd[tid];
    __syncthreads();
    int idx = blockIdx.x * 256 + tid;
    int q = idx >> 4, c0 = (idx & 15) * 4;
    float a0 = sb[c0], a1 = sb[c0 + 1], a2 = sb[c0 + 2], a3 = sb[c0 + 3];
#pragma unroll
    for (int k = 0; k < 27; k++) {
        float dv = g_DIR[q * 32 + k];
        a0 = fmaf(dv, sw[k * 64 + c0 + 0], a0);
        a1 = fmaf(dv, sw[k * 64 + c0 + 1], a1);
        a2 = fmaf(dv, sw[k * 64 + c0 + 2], a2);
        a3 = fmaf(dv, sw[k * 64 + c0 + 3], a3);
    }
    *reinterpret_cast<float4*>(g_V + (size_t)q * 64 + c0) = make_float4(a0, a1, a2, a3);
}

// ---- KNN(16) + interp: clustered queries, ILP2 (2 queries per thread) -----
// Each thread scans all 2048 candidates for TWO adjacent sorted queries:
// one sp[] load feeds both distance chains; two independent insert networks
// overlap in the pipeline. Keys identical to the 1-query version.
#define KNN_SMEM (NC * 16 + 256 * 16 * 4 + 256 * 16 * 4 + 256 * 4)

__global__ void __launch_bounds__(128) knn_interp(const int* __restrict__ indices,
                                                  const float* __restrict__ qp,
                                                  const float* __restrict__ cpos,
                                                  const float* __restrict__ codes) {
    extern __shared__ char ksm[];
    float4* sp  = reinterpret_cast<float4*>(ksm);              // {x,y,z,||c||^2}
    float*  s_w = reinterpret_cast<float*>(ksm + NC * 16);
    int*    s_i = reinterpret_cast<int*>(ksm + NC * 16 + 256 * 16 * 4);
    int*    s_q = reinterpret_cast<int*>(ksm + NC * 16 + 2 * 256 * 16 * 4);

    int tid = threadIdx.x;
    int ib = indices[0];
    const float* cp = cpos + (size_t)ib * NC * 3;
    const float* cc = codes + (size_t)ib * NC * 64;
    for (int c = tid; c < NC; c += 128) {
        float x = cp[c * 3 + 0], y = cp[c * 3 + 1], z = cp[c * 3 + 2];
        sp[c] = make_float4(x, y, z, fmaf(x, x, fmaf(y, y, z * z)));
    }
    __syncthreads();

    int base = blockIdx.x * 256;
    int qA = g_perm[base + 2 * tid];
    int qB = g_perm[base + 2 * tid + 1];
    float ax = qp[qA * 3 + 0], ay = qp[qA * 3 + 1], az = qp[qA * 3 + 2];
    float bx = qp[qB * 3 + 0], by = qp[qB * 3 + 1], bz = qp[qB * 3 + 2];
    float ax2 = -2.f * ax, ay2 = -2.f * ay, az2 = -2.f * az;
    float bx2 = -2.f * bx, by2 = -2.f * by, bz2 = -2.f * bz;
    float a2 = fmaf(ax, ax, fmaf(ay, ay, az * az));
    float b2 = fmaf(bx, bx, fmaf(by, by, bz * bz));

    unsigned bkA[16], bkB[16];
#pragma unroll
    for (int j = 0; j < 16; j++) { bkA[j] = 0x7F7FFFFFu; bkB[j] = 0x7F7FFFFFu; }
    float bndA = __uint_as_float(0x7F7FF800u) - a2;
    float bndB = __uint_as_float(0x7F7FF800u) - b2;

    for (int c = 0; c < NC; c += 4) {
#pragma unroll
        for (int i = 0; i < 4; i++) {
            float4 v = sp[c + i];
            float dpA = fmaf(v.x, ax2, fmaf(v.y, ay2, fmaf(v.z, az2, v.w)));
            float dpB = fmaf(v.x, bx2, fmaf(v.y, by2, fmaf(v.z, bz2, v.w)));
            if (dpA < bndA) {
                float df = fmaxf(dpA + a2, 0.f);
                unsigned cur = (__float_as_uint(df) & 0xFFFFF800u)
                             | (unsigned)(c + i);
#pragma unroll
                for (int j = 0; j < 16; j++) {
                    unsigned mn = min(bkA[j], cur);
                    unsigned mx = max(bkA[j], cur);
                    bkA[j] = mn; cur = mx;
                }
                bndA = __uint_as_float(bkA[15] & 0xFFFFF800u) - a2;
            }
            if (dpB < bndB) {
                float df = fmaxf(dpB + b2, 0.f);
                unsigned cur = (__float_as_uint(df) & 0xFFFFF800u)
                             | (unsigned)(c + i);
#pragma unroll
                for (int j = 0; j < 16; j++) {
                    unsigned mn = min(bkB[j], cur);
                    unsigned mx = max(bkB[j], cur);
                    bkB[j] = mn; cur = mx;
                }
                bndB = __uint_as_float(bkB[15] & 0xFFFFF800u) - b2;
            }
        }
    }

    // exact distances -> normalized 1/d2 weights, for both queries
    {
        float w[16]; int ci[16]; float wsum = 0.f;
#pragma unroll
        for (int k = 0; k < 16; k++) {
            int c = (int)(bkA[k] & 0x7FFu); ci[k] = c;
            float4 v = sp[c];
            float dx = ax - v.x, dy = ay - v.y, dz = az - v.z;
            float d2 = fmaf(dx, dx, fmaf(dy, dy, dz * dz)) + 1e-16f;
            w[k] = 1.0f / d2; wsum += w[k];
        }
        float inv = 1.0f / wsum;
        int sl = 2 * tid;
#pragma unroll
        for (int k = 0; k < 16; k++) {
            s_w[sl * 16 + k] = w[k] * inv;
            s_i[sl * 16 + k] = ci[k];
        }
        s_q[sl] = qA;
    }
    {
        float w[16]; int ci[16]; float wsum = 0.f;
#pragma unroll
        for (int k = 0; k < 16; k++) {
            int c = (int)(bkB[k] & 0x7FFu); ci[k] = c;
            float4 v = sp[c];
            float dx = bx - v.x, dy = by - v.y, dz = bz - v.z;
            float d2 = fmaf(dx, dx, fmaf(dy, dy, dz * dz)) + 1e-16f;
            w[k] = 1.0f / d2; wsum += w[k];
        }
        float inv = 1.0f / wsum;
        int sl = 2 * tid + 1;
#pragma unroll
        for (int k = 0; k < 16; k++) {
            s_w[sl * 16 + k] = w[k] * inv;
            s_i[sl * 16 + k] = ci[k];
        }
        s_q[sl] = qB;
    }
    __syncwarp();   // warp w's 64 slots were written by warp w's own threads

    // warp-cooperative gather: warp w covers slots [w*64, w*64+64)
    int lane = tid & 31;
    int wslot = (tid >> 5) * 64;
    for (int s = 0; s < 64; s++) {
        int sl = wslot + s;
        int qq = s_q[sl];
        float g0 = 0.f, g1 = 0.f;
#pragma unroll
        for (int k = 0; k < 16; k++) {
            int cix = s_i[sl * 16 + k];
            float wk = s_w[sl * 16 + k];
            const float* row = cc + cix * 64;
            g0 = fmaf(wk, row[lane], g0);
            g1 = fmaf(wk, row[lane + 32], g1);
        }
        g_X[(size_t)qq * 128 + lane] = g0;
        g_X[(size_t)qq * 128 + 32 + lane] = g1;
    }
}

// ===================== fused MLP (entire network) ==========================
#define SMEM_FLOATS (128 * AS + 2 * 32 * WS + 128 + 192)

__global__ void __launch_bounds__(256, 2) fused_mlp(
    const float* __restrict__ W1, const float* __restrict__ W3,
    const float* __restrict__ Wf,
    const float* __restrict__ b0, const float* __restrict__ b1,
    const float* __restrict__ b2, const float* __restrict__ b3,
    const float* __restrict__ bf,
    const float* __restrict__ Wsig, const float* __restrict__ bs,
    const float* __restrict__ Wr,   const float* __restrict__ br,
    float* __restrict__ out)
{
    extern __shared__ float sm[];
    float* A   = sm;
    float* Wb  = sm + 128 * AS;
    float* wsv = Wb + 2 * 32 * WS;
    float* wrv = wsv + 128;

    int tid = threadIdx.x;
    int tx = tid & 15, ty = tid >> 4;
    int rowBlk = blockIdx.x * 128;
    const int wbase = tx * 8 + (tx >> 2) * 4;

    if (tid < 128) wsv[tid] = Wsig[tid];
    if (tid < 192) wrv[tid] = Wr[tid];

    {
        const float4* src = reinterpret_cast<const float4*>(g_X + (size_t)rowBlk * 128);
#pragma unroll
        for (int i = 0; i < 16; i++) {
            int f4 = tid + i * 256;
            float4 v = src[f4];
            int row = f4 >> 5, c4 = f4 & 31;
            *reinterpret_cast<float4*>(A + row * AS + c4 * 4) = v;
        }
    }

    const float* Wgs[6] = { g_W2xp, g_W0p, W1, g_W2hp, W3, Wf };
    const float* bgs[6] = { b0, b0, b1, b2, b3, bf };

    float sigR = 0.f;
    ull acc[8][4];

    for (int L = 0; L < 6; ++L) {
        const float* Wg = Wgs[L];
#pragma unroll
        for (int i = 0; i < 8; i++)
#pragma unroll
            for (int j = 0; j < 4; j++) acc[i][j] = 0ULL;

#pragma unroll
        for (int i = 0; i < 4; i++) {
            float4 v = reinterpret_cast<const float4*>(Wg)[tid * 4 + i];
            int flat = tid * 16 + i * 4;
            int k = flat >> 7, col = flat & 127;
            *reinterpret_cast<float4*>(Wb + k * WS + wsw(col)) = v;
        }
        __syncthreads();

        for (int t = 0; t < 4; t++) {
            float4 pf[4];
            if (t < 3) {
                const float4* g = reinterpret_cast<const float4*>(Wg + (t + 1) * 4096);
#pragma unroll
                for (int i = 0; i < 4; i++) pf[i] = g[tid * 4 + i];
            }
            const float* Wt = Wb + (t & 1) * (32 * WS);
#pragma unroll
            for (int k4 = 0; k4 < 8; k4++) {
                ulonglong2 wq0[4], wq1[4];
#pragma unroll
                for (int kk = 0; kk < 4; kk++) {
                    const float* wp = Wt + (k4 * 4 + kk) * WS + wbase;
                    wq0[kk] = *reinterpret_cast<const ulonglong2*>(wp);
                    wq1[kk] = *reinterpret_cast<const ulonglong2*>(wp + 4);
                }
#pragma unroll
                for (int r4 = 0; r4 < 2; r4++) {
                    float4 ar[4];
#pragma unroll
                    for (int r = 0; r < 4; r++)
                        ar[r] = *reinterpret_cast<const float4*>(
                            A + (ty * 8 + r4 * 4 + r) * AS + t * 32 + k4 * 4);
#pragma unroll
                    for (int kk = 0; kk < 4; kk++) {
#pragma unroll
                        for (int r = 0; r < 4; r++) {
                            float av = (kk == 0) ? ar[r].x : (kk == 1) ? ar[r].y
                                     : (kk == 2) ? ar[r].z : ar[r].w;
                            ull ad = pk2(av, av);
                            int ri = r4 * 4 + r;
                            fma2(acc[ri][0], ad, wq0[kk].x);
                            fma2(acc[ri][1], ad, wq0[kk].y);
                            fma2(acc[ri][2], ad, wq1[kk].x);
                            fma2(acc[ri][3], ad, wq1[kk].y);
                        }
                    }
                }
            }
            if (t < 3) {
                float* d = Wb + ((t + 1) & 1) * (32 * WS);
#pragma unroll
                for (int i = 0; i < 4; i++) {
                    int flat = tid * 16 + i * 4;
                    int k = flat >> 7, col = flat & 127;
                    *reinterpret_cast<float4*>(d + k * WS + wsw(col)) = pf[i];
                }
            }
            __syncthreads();
        }

        if (L == 0) {
#pragma unroll
            for (int i = 0; i < 8; i++) {
                size_t row = (size_t)(rowBlk + ty * 8 + i);
                float o[8];
#pragma unroll
                for (int j = 0; j < 4; j++) {
                    float2 v = up2(acc[i][j]); o[2 * j] = v.x; o[2 * j + 1] = v.y;
                }
                *reinterpret_cast<float4*>(g_U + row * 128 + tx * 8) =
                    make_float4(o[0], o[1], o[2], o[3]);
                *reinterpret_cast<float4*>(g_U + row * 128 + tx * 8 + 4) =
                    make_float4(o[4], o[5], o[6], o[7]);
            }
        } else {
            const float* bg = bgs[L];
            float4 bA = *reinterpret_cast<const float4*>(bg + tx * 8);
            float4 bB = *reinterpret_cast<const float4*>(bg + tx * 8 + 4);
            bool relu = (L != 5);
#pragma unroll
            for (int i = 0; i < 8; i++) {
                int row = ty * 8 + i;
                float o[8];
#pragma unroll
                for (int j = 0; j < 4; j++) {
                    float2 v = up2(acc[i][j]); o[2 * j] = v.x; o[2 * j + 1] = v.y;
                }
                if (L == 3) {
                    size_t gr = (size_t)(rowBlk + row);
                    float4 u0 = *reinterpret_cast<const float4*>(g_U + gr * 128 + tx * 8);
                    float4 u1 = *reinterpret_cast<const float4*>(g_U + gr * 128 + tx * 8 + 4);
                    o[0] += u0.x; o[1] += u0.y; o[2] += u0.z; o[3] += u0.w;
                    o[4] += u1.x; o[5] += u1.y; o[6] += u1.z; o[7] += u1.w;
                }
                o[0] += bA.x; o[1] += bA.y; o[2] += bA.z; o[3] += bA.w;
                o[4] += bB.x; o[5] += bB.y; o[6] += bB.z; o[7] += bB.w;
                if (relu) {
#pragma unroll
                    for (int c = 0; c < 8; c++) o[c] = fmaxf(o[c], 0.f);
                }
                *reinterpret_cast<float4*>(A + row * AS + tx * 8) =
                    make_float4(o[0], o[1], o[2], o[3]);
                *reinterpret_cast<float4*>(A + row * AS + tx * 8 + 4) =
                    make_float4(o[4], o[5], o[6], o[7]);
            }
        }
        __syncthreads();

        if (L == 4 && tid < 128) {
            float s = 0.f;
#pragma unroll
            for (int k4 = 0; k4 < 32; k4++) {
                float4 hv = *reinterpret_cast<const float4*>(A + tid * AS + k4 * 4);
                s = fmaf(hv.x, wsv[k4 * 4 + 0], s);
                s = fmaf(hv.y, wsv[k4 * 4 + 1], s);
                s = fmaf(hv.z, wsv[k4 * 4 + 2], s);
                s = fmaf(hv.w, wsv[k4 * 4 + 3], s);
            }
            sigR = s + bs[0];
        }
    }

    // ---- dir layer ----
    int tx8 = tid & 7, ty32 = tid >> 3;
    const int wb64 = tx8 * 8 + (tx8 >> 2) * 4;
    ull acc2[4][4];
#pragma unroll
    for (int i = 0; i < 4; i++)
#pragma unroll
        for (int j = 0; j < 4; j++) acc2[i][j] = 0ULL;

#pragma unroll
    for (int i = 0; i < 2; i++) {
        float4 v = reinterpret_cast<const float4*>(g_Wdfp)[tid * 2 + i];
        int flat = tid * 8 + i * 4;
        int k = flat >> 6, col = flat & 63;
        *reinterpret_cast<float4*>(Wb + k * WS + wsw(col)) = v;
    }
    __syncthreads();

    for (int t = 0; t < 4; t++) {
        float4 pf[2];
        if (t < 3) {
            const float4* g = reinterpret_cast<const float4*>(g_Wdfp + (t + 1) * 2048);
#pragma unroll
            for (int i = 0; i < 2; i++) pf[i] = g[tid * 2 + i];
        }
        const float* Wt = Wb + (t & 1) * (32 * WS);
#pragma unroll
        for (int k4 = 0; k4 < 8; k4++) {
            ulonglong2 wq0[4], wq1[4];
#pragma unroll
            for (int kk = 0; kk < 4; kk++) {
                const float* wp = Wt + (k4 * 4 + kk) * WS + wb64;
                wq0[kk] = *reinterpret_cast<const ulonglong2*>(wp);
                wq1[kk] = *reinterpret_cast<const ulonglong2*>(wp + 4);
            }
            float4 ar[4];
#pragma unroll
            for (int r = 0; r < 4; r++)
                ar[r] = *reinterpret_cast<const float4*>(
                    A + (ty32 * 4 + r) * AS + t * 32 + k4 * 4);
#pragma unroll
            for (int kk = 0; kk < 4; kk++) {
#pragma unroll
                for (int r = 0; r < 4; r++) {
                    float av = (kk == 0) ? ar[r].x : (kk == 1) ? ar[r].y
                             : (kk == 2) ? ar[r].z : ar[r].w;
                    ull ad = pk2(av, av);
                    fma2(acc2[r][0], ad, wq0[kk].x);
                    fma2(acc2[r][1], ad, wq0[kk].y);
                    fma2(acc2[r][2], ad, wq1[kk].x);
                    fma2(acc2[r][3], ad, wq1[kk].y);
                }
            }
        }
        if (t < 3) {
            float* d = Wb + ((t + 1) & 1) * (32 * WS);
#pragma unroll
            for (int i = 0; i < 2; i++) {
                int flat = tid * 8 + i * 4;
                int k = flat >> 6, col = flat & 63;
                *reinterpret_cast<float4*>(d + k * WS + wsw(col)) = pf[i];
            }
        }
        __syncthreads();
    }

#pragma unroll
    for (int r = 0; r < 4; r++) {
        int row = ty32 * 4 + r;
        size_t gr = (size_t)(rowBlk + row);
        float4 v0 = *reinterpret_cast<const float4*>(g_V + gr * 64 + tx8 * 8);
        float4 v1 = *reinterpret_cast<const float4*>(g_V + gr * 64 + tx8 * 8 + 4);
        float o[8];
#pragma unroll
        for (int j = 0; j < 4; j++) {
            float2 v = up2(acc2[r][j]); o[2 * j] = v.x; o[2 * j + 1] = v.y;
        }
        o[0] += v0.x; o[1] += v0.y; o[2] += v0.z; o[3] += v0.w;
        o[4] += v1.x; o[5] += v1.y; o[6] += v1.z; o[7] += v1.w;
#pragma unroll
        for (int c = 0; c < 8; c++) o[c] = fmaxf(o[c], 0.f);
        *reinterpret_cast<float4*>(A + row * AS + tx8 * 8) =
            make_float4(o[0], o[1], o[2], o[3]);
        *reinterpret_cast<float4*>(A + row * AS + tx8 * 8 + 4) =
            make_float4(o[4], o[5], o[6], o[7]);
    }
    __syncthreads();

    if (tid < 128) {
        float r0 = br[0], r1 = br[1], r2 = br[2];
#pragma unroll
        for (int k4 = 0; k4 < 16; k4++) {
            float4 dv = *reinterpret_cast<const float4*>(A + tid * AS + k4 * 4);
            const float* wr0 = wrv + k4 * 12;
            r0 = fmaf(dv.x, wr0[0], r0); r1 = fmaf(dv.x, wr0[1], r1); r2 = fmaf(dv.x, wr0[2], r2);
            r0 = fmaf(dv.y, wr0[3], r0); r1 = fmaf(dv.y, wr0[4], r1); r2 = fmaf(dv.y, wr0[5], r2);
            r0 = fmaf(dv.z, wr0[6], r0); r1 = fmaf(dv.z, wr0[7], r1); r2 = fmaf(dv.z, wr0[8], r2);
            r0 = fmaf(dv.w, wr0[9], r0); r1 = fmaf(dv.w, wr0[10], r1); r2 = fmaf(dv.w, wr0[11], r2);
        }
        *reinterpret_cast<float4*>(out + (size_t)(rowBlk + tid) * 4) =
            make_float4(r0, r1, r2, sigR);
    }
}

// ---------------------------------------------------------------------------
extern "C" void kernel_launch(void* const* d_in, const int* in_sizes, int n_in,
                              void* d_out, int out_size) {
    const int*   indices = (const int*)  d_in[0];
    const float* qp      = (const float*)d_in[1];
    const float* xyzdir  = (const float*)d_in[2];
    const float* cpos    = (const float*)d_in[3];
    const float* codes   = (const float*)d_in[4];
    const float* W0 = (const float*)d_in[5],  *b0 = (const float*)d_in[6];
    const float* W1 = (const float*)d_in[7],  *b1 = (const float*)d_in[8];
    const float* W2 = (const float*)d_in[9],  *b2 = (const float*)d_in[10];
    const float* W3 = (const float*)d_in[11], *b3 = (const float*)d_in[12];
    const float* Wf = (const float*)d_in[13], *bf = (const float*)d_in[14];
    const float* Wd = (const float*)d_in[15], *bd = (const float*)d_in[16];
    const float* Ws = (const float*)d_in[17], *bs = (const float*)d_in[18];
    const float* Wr = (const float*)d_in[19], *br = (const float*)d_in[20];
    float* out = (float*)d_out;

    const int smemBytes = SMEM_FLOATS * 4;
    cudaFuncSetAttribute(fused_mlp, cudaFuncAttributeMaxDynamicSharedMemorySize,
                         smemBytes);
    cudaFuncSetAttribute(knn_interp, cudaFuncAttributeMaxDynamicSharedMemorySize,
                         KNN_SMEM);

    zero_hist<<<16, 256>>>();
    hist_k<<<NQ / 256, 256>>>(qp);
    scan_k<<<1, 1024>>>();
    scatter_k<<<NQ / 256, 256>>>(qp);
    prep_weights<<<224, 256>>>(W0, W2, Wd);
    pack_inputs<<<1024, 256>>>(xyzdir);
    vcomp<<<NQ * 16 / 256, 256>>>(Wd, bd);
    knn_interp<<<NQ / 256, 128, KNN_SMEM>>>(indices, qp, cpos, codes);
    fused_mlp<<<NQ / 128, 256, smemBytes>>>(W1, W3, Wf, b0, b1, b2, b3, bf,
                                            Ws, bs, Wr, br, out);
}

// round 11
// speedup vs baseline: 1.1540x; 1.1345x over previous
#include <cuda_runtime.h>
#include <cstdint>

#define NQ 65536
#define NC 2048
#define AS 132   // activation smem row stride (floats)
#define WS 144   // weight-tile smem row stride (floats)

typedef unsigned long long ull;

// ------- device scratch (static __device__ globals: allocation-free) -------
__device__ float g_X[NQ * 128];    // [query_codes 64 | xyz_emb 63 | 0]
__device__ float g_U[NQ * 128];    // X @ W2x   (skip-path partial)
__device__ float g_V[NQ * 64];     // dir @ Wd_dir + bd
__device__ int   g_hist[4096];
__device__ int   g_offs[4096];
__device__ int   g_perm[NQ];
__device__ float g_W0p[128 * 128];
__device__ float g_W2xp[128 * 128];
__device__ float g_W2hp[128 * 128];
__device__ float g_Wdfp[128 * 64];

// ------------------------- f32x2 helpers -----------------------------------
__device__ __forceinline__ ull pk2(float lo, float hi) {
    ull r; asm("mov.b64 %0,{%1,%2};" : "=l"(r) : "f"(lo), "f"(hi)); return r;
}
__device__ __forceinline__ void fma2(ull& c, ull a, ull b) {
    asm("fma.rn.f32x2 %0,%1,%2,%0;" : "+l"(c) : "l"(a), "l"(b));
}
__device__ __forceinline__ float2 up2(ull v) {
    float2 r; asm("mov.b64 {%0,%1},%2;" : "=f"(r.x), "=f"(r.y) : "l"(v)); return r;
}
__device__ __forceinline__ int wsw(int col) {
    int g = col >> 3;
    return g * 8 + (g >> 2) * 4 + (col & 7);
}
__device__ __forceinline__ int cell_of(float x, float y, float z) {
    int ix = min(15, max(0, (int)(x * 16.f)));
    int iy = min(15, max(0, (int)(y * 16.f)));
    int iz = min(15, max(0, (int)(z * 16.f)));
    return (ix << 8) | (iy << 4) | iz;
}

// --------------------- spatial counting sort of queries --------------------
__global__ void hist_k(const float* __restrict__ qp) {
    int q = blockIdx.x * 256 + threadIdx.x;
    atomicAdd(&g_hist[cell_of(qp[3 * q], qp[3 * q + 1], qp[3 * q + 2])], 1);
}

__global__ void __launch_bounds__(1024) scan_k() {   // 1 block
    __shared__ int s[1024];
    int tid = threadIdx.x;
    int v[4]; int sum = 0;
#pragma unroll
    for (int i = 0; i < 4; i++) { v[i] = g_hist[tid * 4 + i]; sum += v[i]; }
    s[tid] = sum; __syncthreads();
    for (int off = 1; off < 1024; off <<= 1) {
        int t = (tid >= off) ? s[tid - off] : 0;
        __syncthreads();
        s[tid] += t;
        __syncthreads();
    }
    int run = tid ? s[tid - 1] : 0;
#pragma unroll
    for (int i = 0; i < 4; i++) { g_offs[tid * 4 + i] = run; run += v[i]; }
}

__global__ void scatter_k(const float* __restrict__ qp) {
    int q = blockIdx.x * 256 + threadIdx.x;
    int cell = cell_of(qp[3 * q], qp[3 * q + 1], qp[3 * q + 2]);
    int pos = atomicAdd(&g_offs[cell], 1);
    g_perm[pos] = q;
}

// ------ merged prologue: weight prep | xyz pack | V = dir@Wd_dir + bd ------
// blocks [0,224): weight padding/splitting
// blocks [224,1248): pack xyz embedding into g_X cols 64..127 (grid-stride)
// blocks [1248,5344): V computation, one (q, c0) chunk per thread
__global__ void __launch_bounds__(256) prologue_k(const float* __restrict__ W0,
                                                  const float* __restrict__ W2,
                                                  const float* __restrict__ Wd,
                                                  const float* __restrict__ bd,
                                                  const float* __restrict__ xyzdir) {
    int bid = blockIdx.x;
    int tid = threadIdx.x;
    if (bid < 224) {
        const int T0 = 16384, T1 = 16384, T2 = 16384, T3 = 8192;
        int total = T0 + T1 + T2 + T3;
        for (int i = bid * 256 + tid; i < total; i += 224 * 256) {
            if (i < T0) {
                int r = i >> 7, c = i & 127;
                g_W0p[i] = (r < 127) ? W0[r * 128 + c] : 0.f;
            } else if (i < T0 + T1) {
                int j = i - T0; int r = j >> 7, c = j & 127;
                g_W2xp[j] = (r < 127) ? W2[r * 128 + c] : 0.f;
            } else if (i < T0 + T1 + T2) {
                int j = i - T0 - T1; int r = j >> 7, c = j & 127;
                g_W2hp[j] = W2[(127 + r) * 128 + c];
            } else {
                int j = i - T0 - T1 - T2;
                g_Wdfp[j] = Wd[j];
            }
        }
    } else if (bid < 1248) {
        const int total = NQ * 64;
        for (int i = (bid - 224) * 256 + tid; i < total; i += 1024 * 256) {
            int q = i >> 6, e = i & 63;
            g_X[q * 128 + 64 + e] = (e < 63) ? xyzdir[q * 90 + e] : 0.f;
        }
    } else {
        __shared__ float sw[27 * 64];
        __shared__ float sb[64];
        for (int i = tid; i < 27 * 64; i += 256) sw[i] = Wd[128 * 64 + i];
        if (tid < 64) sb[tid] = bd[tid];
        __syncthreads();
        int idx = (bid - 1248) * 256 + tid;     // NQ*16 threads
        int q = idx >> 4, c0 = (idx & 15) * 4;
        float a0 = sb[c0], a1 = sb[c0 + 1], a2 = sb[c0 + 2], a3 = sb[c0 + 3];
        const float* dirp = xyzdir + (size_t)q * 90 + 63;
#pragma unroll
        for (int k = 0; k < 27; k++) {
            float dv = dirp[k];
            a0 = fmaf(dv, sw[k * 64 + c0 + 0], a0);
            a1 = fmaf(dv, sw[k * 64 + c0 + 1], a1);
            a2 = fmaf(dv, sw[k * 64 + c0 + 2], a2);
            a3 = fmaf(dv, sw[k * 64 + c0 + 3], a3);
        }
        *reinterpret_cast<float4*>(g_V + (size_t)q * 64 + c0) =
            make_float4(a0, a1, a2, a3);
    }
}

// --------- KNN(16) + interpolation, fused; clustered queries ---------------
__global__ void __launch_bounds__(128) knn_interp(const int* __restrict__ indices,
                                                  const float* __restrict__ qp,
                                                  const float* __restrict__ cpos,
                                                  const float* __restrict__ codes) {
    __shared__ float4 sp[NC];      // {x, y, z, ||c||^2}
    __shared__ float s_w[128 * 16];
    __shared__ int   s_i[128 * 16];
    int tid = threadIdx.x;
    int ib = indices[0];
    const float* cp = cpos + (size_t)ib * NC * 3;
    const float* cc = codes + (size_t)ib * NC * 64;
    for (int c = tid; c < NC; c += 128) {
        float x = cp[c * 3 + 0], y = cp[c * 3 + 1], z = cp[c * 3 + 2];
        sp[c] = make_float4(x, y, z, fmaf(x, x, fmaf(y, y, z * z)));
    }
    __syncthreads();

    int q = g_perm[blockIdx.x * 128 + tid];
    float qx = qp[q * 3 + 0], qy = qp[q * 3 + 1], qz = qp[q * 3 + 2];
    float qx2 = -2.f * qx, qy2 = -2.f * qy, qz2 = -2.f * qz;
    float q2 = fmaf(qx, qx, fmaf(qy, qy, qz * qz));

    unsigned bk[16];
#pragma unroll
    for (int j = 0; j < 16; j++) bk[j] = 0x7F7FFFFFu;
    float bnd = __uint_as_float(0x7F7FF800u) - q2;   // d2' threshold

    for (int c = 0; c < NC; c += 4) {
#pragma unroll
        for (int i = 0; i < 4; i++) {
            float4 v = sp[c + i];
            float dp = fmaf(v.x, qx2, fmaf(v.y, qy2, fmaf(v.z, qz2, v.w)));
            if (dp < bnd) {
                float dfull = fmaxf(dp + q2, 0.f);   // clamp: keep bits ordered
                unsigned cur = (__float_as_uint(dfull) & 0xFFFFF800u)
                             | (unsigned)(c + i);
#pragma unroll
                for (int j = 0; j < 16; j++) {
                    unsigned mn = min(bk[j], cur);
                    unsigned mx = max(bk[j], cur);
                    bk[j] = mn; cur = mx;
                }
                bnd = __uint_as_float(bk[15] & 0xFFFFF800u) - q2;
            }
        }
    }

    // exact distances -> normalized 1/d2 weights
    float w[16]; int ci[16]; float wsum = 0.f;
#pragma unroll
    for (int k = 0; k < 16; k++) {
        int c = (int)(bk[k] & 0x7FFu); ci[k] = c;
        float4 v = sp[c];
        float dx = qx - v.x, dy = qy - v.y, dz = qz - v.z;
        float d2 = fmaf(dx, dx, fmaf(dy, dy, dz * dz)) + 1e-16f;
        w[k] = 1.0f / d2; wsum += w[k];
    }
    float inv = 1.0f / wsum;
#pragma unroll
    for (int k = 0; k < 16; k++) {
        s_w[tid * 16 + k] = w[k] * inv;
        s_i[tid * 16 + k] = ci[k];
    }
    __syncwarp();

    // warp-cooperative gather: lanes cover 64 code dims, coalesced rows
    int lane = tid & 31;
    int wbase2 = tid & ~31;
    for (int s = 0; s < 32; s++) {
        int t = wbase2 + s;
        int qq = __shfl_sync(0xFFFFFFFFu, q, s);
        float a0 = 0.f, a1 = 0.f;
#pragma unroll
        for (int k = 0; k < 16; k++) {
            int cix = s_i[t * 16 + k];
            float wk = s_w[t * 16 + k];
            const float* row = cc + cix * 64;
            a0 = fmaf(wk, row[lane], a0);
            a1 = fmaf(wk, row[lane + 32], a1);
        }
        g_X[(size_t)qq * 128 + lane] = a0;
        g_X[(size_t)qq * 128 + 32 + lane] = a1;
    }
}

// ===================== fused MLP (entire network) ==========================
#define SMEM_FLOATS (128 * AS + 2 * 32 * WS + 128 + 192)

__global__ void __launch_bounds__(256, 2) fused_mlp(
    const float* __restrict__ W1, const float* __restrict__ W3,
    const float* __restrict__ Wf,
    const float* __restrict__ b0, const float* __restrict__ b1,
    const float* __restrict__ b2, const float* __restrict__ b3,
    const float* __restrict__ bf,
    const float* __restrict__ Wsig, const float* __restrict__ bs,
    const float* __restrict__ Wr,   const float* __restrict__ br,
    float* __restrict__ out)
{
    extern __shared__ float sm[];
    float* A   = sm;
    float* Wb  = sm + 128 * AS;
    float* wsv = Wb + 2 * 32 * WS;
    float* wrv = wsv + 128;

    int tid = threadIdx.x;
    int tx = tid & 15, ty = tid >> 4;
    int rowBlk = blockIdx.x * 128;
    const int wbase = tx * 8 + (tx >> 2) * 4;

    if (tid < 128) wsv[tid] = Wsig[tid];
    if (tid < 192) wrv[tid] = Wr[tid];

    {
        const float4* src = reinterpret_cast<const float4*>(g_X + (size_t)rowBlk * 128);
#pragma unroll
        for (int i = 0; i < 16; i++) {
            int f4 = tid + i * 256;
            float4 v = src[f4];
            int row = f4 >> 5, c4 = f4 & 31;
            *reinterpret_cast<float4*>(A + row * AS + c4 * 4) = v;
        }
    }

    const float* Wgs[6] = { g_W2xp, g_W0p, W1, g_W2hp, W3, Wf };
    const float* bgs[6] = { b0, b0, b1, b2, b3, bf };

    float sigR = 0.f;
    ull acc[8][4];

    for (int L = 0; L < 6; ++L) {
        const float* Wg = Wgs[L];
#pragma unroll
        for (int i = 0; i < 8; i++)
#pragma unroll
            for (int j = 0; j < 4; j++) acc[i][j] = 0ULL;

#pragma unroll
        for (int i = 0; i < 4; i++) {
            float4 v = reinterpret_cast<const float4*>(Wg)[tid * 4 + i];
            int flat = tid * 16 + i * 4;
            int k = flat >> 7, col = flat & 127;
            *reinterpret_cast<float4*>(Wb + k * WS + wsw(col)) = v;
        }
        __syncthreads();

        for (int t = 0; t < 4; t++) {
            float4 pf[4];
            if (t < 3) {
                const float4* g = reinterpret_cast<const float4*>(Wg + (t + 1) * 4096);
#pragma unroll
                for (int i = 0; i < 4; i++) pf[i] = g[tid * 4 + i];
            }
            const float* Wt = Wb + (t & 1) * (32 * WS);
#pragma unroll
            for (int k4 = 0; k4 < 8; k4++) {
                ulonglong2 wq0[4], wq1[4];
#pragma unroll
                for (int kk = 0; kk < 4; kk++) {
                    const float* wp = Wt + (k4 * 4 + kk) * WS + wbase;
                    wq0[kk] = *reinterpret_cast<const ulonglong2*>(wp);
                    wq1[kk] = *reinterpret_cast<const ulonglong2*>(wp + 4);
                }
#pragma unroll
                for (int r4 = 0; r4 < 2; r4++) {
                    float4 ar[4];
#pragma unroll
                    for (int r = 0; r < 4; r++)
                        ar[r] = *reinterpret_cast<const float4*>(
                            A + (ty * 8 + r4 * 4 + r) * AS + t * 32 + k4 * 4);
#pragma unroll
                    for (int kk = 0; kk < 4; kk++) {
#pragma unroll
                        for (int r = 0; r < 4; r++) {
                            float av = (kk == 0) ? ar[r].x : (kk == 1) ? ar[r].y
                                     : (kk == 2) ? ar[r].z : ar[r].w;
                            ull ad = pk2(av, av);
                            int ri = r4 * 4 + r;
                            fma2(acc[ri][0], ad, wq0[kk].x);
                            fma2(acc[ri][1], ad, wq0[kk].y);
                            fma2(acc[ri][2], ad, wq1[kk].x);
                            fma2(acc[ri][3], ad, wq1[kk].y);
                        }
                    }
                }
            }
            if (t < 3) {
                float* d = Wb + ((t + 1) & 1) * (32 * WS);
#pragma unroll
                for (int i = 0; i < 4; i++) {
                    int flat = tid * 16 + i * 4;
                    int k = flat >> 7, col = flat & 127;
                    *reinterpret_cast<float4*>(d + k * WS + wsw(col)) = pf[i];
                }
            }
            __syncthreads();
        }

        if (L == 0) {
#pragma unroll
            for (int i = 0; i < 8; i++) {
                size_t row = (size_t)(rowBlk + ty * 8 + i);
                float o[8];
#pragma unroll
                for (int j = 0; j < 4; j++) {
                    float2 v = up2(acc[i][j]); o[2 * j] = v.x; o[2 * j + 1] = v.y;
                }
                *reinterpret_cast<float4*>(g_U + row * 128 + tx * 8) =
                    make_float4(o[0], o[1], o[2], o[3]);
                *reinterpret_cast<float4*>(g_U + row * 128 + tx * 8 + 4) =
                    make_float4(o[4], o[5], o[6], o[7]);
            }
        } else {
            const float* bg = bgs[L];
            float4 bA = *reinterpret_cast<const float4*>(bg + tx * 8);
            float4 bB = *reinterpret_cast<const float4*>(bg + tx * 8 + 4);
            bool relu = (L != 5);
#pragma unroll
            for (int i = 0; i < 8; i++) {
                int row = ty * 8 + i;
                float o[8];
#pragma unroll
                for (int j = 0; j < 4; j++) {
                    float2 v = up2(acc[i][j]); o[2 * j] = v.x; o[2 * j + 1] = v.y;
                }
                if (L == 3) {
                    size_t gr = (size_t)(rowBlk + row);
                    float4 u0 = *reinterpret_cast<const float4*>(g_U + gr * 128 + tx * 8);
                    float4 u1 = *reinterpret_cast<const float4*>(g_U + gr * 128 + tx * 8 + 4);
                    o[0] += u0.x; o[1] += u0.y; o[2] += u0.z; o[3] += u0.w;
                    o[4] += u1.x; o[5] += u1.y; o[6] += u1.z; o[7] += u1.w;
                }
                o[0] += bA.x; o[1] += bA.y; o[2] += bA.z; o[3] += bA.w;
                o[4] += bB.x; o[5] += bB.y; o[6] += bB.z; o[7] += bB.w;
                if (relu) {
#pragma unroll
                    for (int c = 0; c < 8; c++) o[c] = fmaxf(o[c], 0.f);
                }
                *reinterpret_cast<float4*>(A + row * AS + tx * 8) =
                    make_float4(o[0], o[1], o[2], o[3]);
                *reinterpret_cast<float4*>(A + row * AS + tx * 8 + 4) =
                    make_float4(o[4], o[5], o[6], o[7]);
            }
        }
        __syncthreads();

        if (L == 4 && tid < 128) {
            float s = 0.f;
#pragma unroll
            for (int k4 = 0; k4 < 32; k4++) {
                float4 hv = *reinterpret_cast<const float4*>(A + tid * AS + k4 * 4);
                s = fmaf(hv.x, wsv[k4 * 4 + 0], s);
                s = fmaf(hv.y, wsv[k4 * 4 + 1], s);
                s = fmaf(hv.z, wsv[k4 * 4 + 2], s);
                s = fmaf(hv.w, wsv[k4 * 4 + 3], s);
            }
            sigR = s + bs[0];
        }
    }

    // ---- dir layer ----
    int tx8 = tid & 7, ty32 = tid >> 3;
    const int wb64 = tx8 * 8 + (tx8 >> 2) * 4;
    ull acc2[4][4];
#pragma unroll
    for (int i = 0; i < 4; i++)
#pragma unroll
        for (int j = 0; j < 4; j++) acc2[i][j] = 0ULL;

#pragma unroll
    for (int i = 0; i < 2; i++) {
        float4 v = reinterpret_cast<const float4*>(g_Wdfp)[tid * 2 + i];
        int flat = tid * 8 + i * 4;
        int k = flat >> 6, col = flat & 63;
        *reinterpret_cast<float4*>(Wb + k * WS + wsw(col)) = v;
    }
    __syncthreads();

    for (int t = 0; t < 4; t++) {
        float4 pf[2];
        if (t < 3) {
            const float4* g = reinterpret_cast<const float4*>(g_Wdfp + (t + 1) * 2048);
#pragma unroll
            for (int i = 0; i < 2; i++) pf[i] = g[tid * 2 + i];
        }
        const float* Wt = Wb + (t & 1) * (32 * WS);
#pragma unroll
        for (int k4 = 0; k4 < 8; k4++) {
            ulonglong2 wq0[4], wq1[4];
#pragma unroll
            for (int kk = 0; kk < 4; kk++) {
                const float* wp = Wt + (k4 * 4 + kk) * WS + wb64;
                wq0[kk] = *reinterpret_cast<const ulonglong2*>(wp);
                wq1[kk] = *reinterpret_cast<const ulonglong2*>(wp + 4);
            }
            float4 ar[4];
#pragma unroll
            for (int r = 0; r < 4; r++)
                ar[r] = *reinterpret_cast<const float4*>(
                    A + (ty32 * 4 + r) * AS + t * 32 + k4 * 4);
#pragma unroll
            for (int kk = 0; kk < 4; kk++) {
#pragma unroll
                for (int r = 0; r < 4; r++) {
                    float av = (kk == 0) ? ar[r].x : (kk == 1) ? ar[r].y
                             : (kk == 2) ? ar[r].z : ar[r].w;
                    ull ad = pk2(av, av);
                    fma2(acc2[r][0], ad, wq0[kk].x);
                    fma2(acc2[r][1], ad, wq0[kk].y);
                    fma2(acc2[r][2], ad, wq1[kk].x);
                    fma2(acc2[r][3], ad, wq1[kk].y);
                }
            }
        }
        if (t < 3) {
            float* d = Wb + ((t + 1) & 1) * (32 * WS);
#pragma unroll
            for (int i = 0; i < 2; i++) {
                int flat = tid * 8 + i * 4;
                int k = flat >> 6, col = flat & 63;
                *reinterpret_cast<float4*>(d + k * WS + wsw(col)) = pf[i];
            }
        }
        __syncthreads();
    }

#pragma unroll
    for (int r = 0; r < 4; r++) {
        int row = ty32 * 4 + r;
        size_t gr = (size_t)(rowBlk + row);
        float4 v0 = *reinterpret_cast<const float4*>(g_V + gr * 64 + tx8 * 8);
        float4 v1 = *reinterpret_cast<const float4*>(g_V + gr * 64 + tx8 * 8 + 4);
        float o[8];
#pragma unroll
        for (int j = 0; j < 4; j++) {
            float2 v = up2(acc2[r][j]); o[2 * j] = v.x; o[2 * j + 1] = v.y;
        }
        o[0] += v0.x; o[1] += v0.y; o[2] += v0.z; o[3] += v0.w;
        o[4] += v1.x; o[5] += v1.y; o[6] += v1.z; o[7] += v1.w;
#pragma unroll
        for (int c = 0; c < 8; c++) o[c] = fmaxf(o[c], 0.f);
        *reinterpret_cast<float4*>(A + row * AS + tx8 * 8) =
            make_float4(o[0], o[1], o[2], o[3]);
        *reinterpret_cast<float4*>(A + row * AS + tx8 * 8 + 4) =
            make_float4(o[4], o[5], o[6], o[7]);
    }
    __syncthreads();

    if (tid < 128) {
        float r0 = br[0], r1 = br[1], r2 = br[2];
#pragma unroll
        for (int k4 = 0; k4 < 16; k4++) {
            float4 dv = *reinterpret_cast<const float4*>(A + tid * AS + k4 * 4);
            const float* wr0 = wrv + k4 * 12;
            r0 = fmaf(dv.x, wr0[0], r0); r1 = fmaf(dv.x, wr0[1], r1); r2 = fmaf(dv.x, wr0[2], r2);
            r0 = fmaf(dv.y, wr0[3], r0); r1 = fmaf(dv.y, wr0[4], r1); r2 = fmaf(dv.y, wr0[5], r2);
            r0 = fmaf(dv.z, wr0[6], r0); r1 = fmaf(dv.z, wr0[7], r1); r2 = fmaf(dv.z, wr0[8], r2);
            r0 = fmaf(dv.w, wr0[9], r0); r1 = fmaf(dv.w, wr0[10], r1); r2 = fmaf(dv.w, wr0[11], r2);
        }
        *reinterpret_cast<float4*>(out + (size_t)(rowBlk + tid) * 4) =
            make_float4(r0, r1, r2, sigR);
    }
}

// ---------------------------------------------------------------------------
extern "C" void kernel_launch(void* const* d_in, const int* in_sizes, int n_in,
                              void* d_out, int out_size) {
    const int*   indices = (const int*)  d_in[0];
    const float* qp      = (const float*)d_in[1];
    const float* xyzdir  = (const float*)d_in[2];
    const float* cpos    = (const float*)d_in[3];
    const float* codes   = (const float*)d_in[4];
    const float* W0 = (const float*)d_in[5],  *b0 = (const float*)d_in[6];
    const float* W1 = (const float*)d_in[7],  *b1 = (const float*)d_in[8];
    const float* W2 = (const float*)d_in[9],  *b2 = (const float*)d_in[10];
    const float* W3 = (const float*)d_in[11], *b3 = (const float*)d_in[12];
    const float* Wf = (const float*)d_in[13], *bf = (const float*)d_in[14];
    const float* Wd = (const float*)d_in[15], *bd = (const float*)d_in[16];
    const float* Ws = (const float*)d_in[17], *bs = (const float*)d_in[18];
    const float* Wr = (const float*)d_in[19], *br = (const float*)d_in[20];
    float* out = (float*)d_out;

    const int smemBytes = SMEM_FLOATS * 4;
    cudaFuncSetAttribute(fused_mlp, cudaFuncAttributeMaxDynamicSharedMemorySize,
                         smemBytes);

    void* histPtr = nullptr;
    cudaGetSymbolAddress(&histPtr, g_hist);
    cudaMemsetAsync(histPtr, 0, 4096 * sizeof(int));

    hist_k<<<NQ / 256, 256>>>(qp);
    prologue_k<<<5344, 256>>>(W0, W2, Wd, bd, xyzdir);
    scan_k<<<1, 1024>>>();
    scatter_k<<<NQ / 256, 256>>>(qp);
    knn_interp<<<NQ / 128, 128>>>(indices, qp, cpos, codes);
    fused_mlp<<<NQ / 128, 256, smemBytes>>>(W1, W3, Wf, b0, b1, b2, b3, bf,
                                            Ws, bs, Wr, br, out);
}

// round 12
// speedup vs baseline: 2.1286x; 1.8445x over previous
#include <cuda_runtime.h>
#include <cstdint>

#define NQ 65536
#define NC 2048
#define ASM 132   // activation smem row stride (floats), 132 % 32 == 4
#define WSM 136   // weight-tile smem row stride (floats), 136 % 32 == 8

typedef unsigned long long ull;

// ------- device scratch (static __device__ globals: allocation-free) -------
__device__ float g_X[NQ * 128];    // tf32-rounded [query_codes 64 | xyz 63 | 0]
__device__ float g_V[NQ * 64];     // dir @ Wd_dir + bd  (fp32)
__device__ int   g_hist[4096];
__device__ int   g_offs[4096];
__device__ int   g_perm[NQ];
__device__ float g_W0p[128 * 128]; // all weights tf32-rounded, padded
__device__ float g_W1p[128 * 128];
__device__ float g_W2xp[128 * 128];
__device__ float g_W2hp[128 * 128];
__device__ float g_W3p[128 * 128];
__device__ float g_Wfp[128 * 128];
__device__ float g_Wdfp[128 * 64];

// ------------------------- helpers -----------------------------------------
__device__ __forceinline__ float to_tf32(float x) {
    float r; asm("cvt.rna.tf32.f32 %0, %1;" : "=f"(r) : "f"(x)); return r;
}
__device__ __forceinline__ void mma8(float* c, const float* a, float b0, float b1) {
    asm volatile(
        "mma.sync.aligned.m16n8k8.row.col.f32.tf32.tf32.f32 "
        "{%0,%1,%2,%3}, {%4,%5,%6,%7}, {%8,%9}, {%0,%1,%2,%3};"
        : "+f"(c[0]), "+f"(c[1]), "+f"(c[2]), "+f"(c[3])
        : "r"(__float_as_uint(a[0])), "r"(__float_as_uint(a[1])),
          "r"(__float_as_uint(a[2])), "r"(__float_as_uint(a[3])),
          "r"(__float_as_uint(b0)), "r"(__float_as_uint(b1)));
}
__device__ __forceinline__ int cell_of(float x, float y, float z) {
    int ix = min(15, max(0, (int)(x * 16.f)));
    int iy = min(15, max(0, (int)(y * 16.f)));
    int iz = min(15, max(0, (int)(z * 16.f)));
    return (ix << 8) | (iy << 4) | iz;
}

// --------------------- spatial counting sort of queries --------------------
__global__ void hist_k(const float* __restrict__ qp) {
    int q = blockIdx.x * 256 + threadIdx.x;
    atomicAdd(&g_hist[cell_of(qp[3 * q], qp[3 * q + 1], qp[3 * q + 2])], 1);
}

__global__ void __launch_bounds__(1024) scan_k() {   // 1 block
    __shared__ int s[1024];
    int tid = threadIdx.x;
    int v[4]; int sum = 0;
#pragma unroll
    for (int i = 0; i < 4; i++) { v[i] = g_hist[tid * 4 + i]; sum += v[i]; }
    s[tid] = sum; __syncthreads();
    for (int off = 1; off < 1024; off <<= 1) {
        int t = (tid >= off) ? s[tid - off] : 0;
        __syncthreads();
        s[tid] += t;
        __syncthreads();
    }
    int run = tid ? s[tid - 1] : 0;
#pragma unroll
    for (int i = 0; i < 4; i++) { g_offs[tid * 4 + i] = run; run += v[i]; }
}

__global__ void scatter_k(const float* __restrict__ qp) {
    int q = blockIdx.x * 256 + threadIdx.x;
    int cell = cell_of(qp[3 * q], qp[3 * q + 1], qp[3 * q + 2]);
    int pos = atomicAdd(&g_offs[cell], 1);
    g_perm[pos] = q;
}

// ------ merged prologue: weight prep (tf32) | xyz pack | V comp ------------
__global__ void __launch_bounds__(256) prologue_k(
        const float* __restrict__ W0, const float* __restrict__ W1,
        const float* __restrict__ W2, const float* __restrict__ W3,
        const float* __restrict__ Wf, const float* __restrict__ Wd,
        const float* __restrict__ bd, const float* __restrict__ xyzdir) {
    int bid = blockIdx.x;
    int tid = threadIdx.x;
    const int T = 16384;
    if (bid < 224) {
        int total = 6 * T + 8192;
        for (int i = bid * 256 + tid; i < total; i += 224 * 256) {
            if (i < T) {
                int r = i >> 7, c = i & 127;
                g_W0p[i] = (r < 127) ? to_tf32(W0[r * 128 + c]) : 0.f;
            } else if (i < 2 * T) {
                int j = i - T;
                g_W1p[j] = to_tf32(W1[j]);
            } else if (i < 3 * T) {
                int j = i - 2 * T; int r = j >> 7, c = j & 127;
                g_W2xp[j] = (r < 127) ? to_tf32(W2[r * 128 + c]) : 0.f;
            } else if (i < 4 * T) {
                int j = i - 3 * T; int r = j >> 7, c = j & 127;
                g_W2hp[j] = to_tf32(W2[(127 + r) * 128 + c]);
            } else if (i < 5 * T) {
                int j = i - 4 * T;
                g_W3p[j] = to_tf32(W3[j]);
            } else if (i < 6 * T) {
                int j = i - 5 * T;
                g_Wfp[j] = to_tf32(Wf[j]);
            } else {
                int j = i - 6 * T;
                g_Wdfp[j] = to_tf32(Wd[j]);
            }
        }
    } else if (bid < 1248) {
        const int total = NQ * 64;
        for (int i = (bid - 224) * 256 + tid; i < total; i += 1024 * 256) {
            int q = i >> 6, e = i & 63;
            g_X[q * 128 + 64 + e] = (e < 63) ? to_tf32(xyzdir[q * 90 + e]) : 0.f;
        }
    } else {
        __shared__ float sw[27 * 64];
        __shared__ float sb[64];
        for (int i = tid; i < 27 * 64; i += 256) sw[i] = Wd[128 * 64 + i];
        if (tid < 64) sb[tid] = bd[tid];
        __syncthreads();
        int idx = (bid - 1248) * 256 + tid;     // NQ*16 threads
        int q = idx >> 4, c0 = (idx & 15) * 4;
        float a0 = sb[c0], a1 = sb[c0 + 1], a2 = sb[c0 + 2], a3 = sb[c0 + 3];
        const float* dirp = xyzdir + (size_t)q * 90 + 63;
#pragma unroll
        for (int k = 0; k < 27; k++) {
            float dv = dirp[k];
            a0 = fmaf(dv, sw[k * 64 + c0 + 0], a0);
            a1 = fmaf(dv, sw[k * 64 + c0 + 1], a1);
            a2 = fmaf(dv, sw[k * 64 + c0 + 2], a2);
            a3 = fmaf(dv, sw[k * 64 + c0 + 3], a3);
        }
        *reinterpret_cast<float4*>(g_V + (size_t)q * 64 + c0) =
            make_float4(a0, a1, a2, a3);
    }
}

// --------- KNN(16) + interpolation, fused; clustered queries ---------------
__global__ void __launch_bounds__(128) knn_interp(const int* __restrict__ indices,
                                                  const float* __restrict__ qp,
                                                  const float* __restrict__ cpos,
                                                  const float* __restrict__ codes) {
    __shared__ float4 sp[NC];      // {x, y, z, ||c||^2}
    __shared__ float s_w[128 * 16];
    __shared__ int   s_i[128 * 16];
    int tid = threadIdx.x;
    int ib = indices[0];
    const float* cp = cpos + (size_t)ib * NC * 3;
    const float* cc = codes + (size_t)ib * NC * 64;
    for (int c = tid; c < NC; c += 128) {
        float x = cp[c * 3 + 0], y = cp[c * 3 + 1], z = cp[c * 3 + 2];
        sp[c] = make_float4(x, y, z, fmaf(x, x, fmaf(y, y, z * z)));
    }
    __syncthreads();

    int q = g_perm[blockIdx.x * 128 + tid];
    float qx = qp[q * 3 + 0], qy = qp[q * 3 + 1], qz = qp[q * 3 + 2];
    float qx2 = -2.f * qx, qy2 = -2.f * qy, qz2 = -2.f * qz;
    float q2 = fmaf(qx, qx, fmaf(qy, qy, qz * qz));

    unsigned bk[16];
#pragma unroll
    for (int j = 0; j < 16; j++) bk[j] = 0x7F7FFFFFu;
    float bnd = __uint_as_float(0x7F7FF800u) - q2;

    for (int c = 0; c < NC; c += 4) {
#pragma unroll
        for (int i = 0; i < 4; i++) {
            float4 v = sp[c + i];
            float dp = fmaf(v.x, qx2, fmaf(v.y, qy2, fmaf(v.z, qz2, v.w)));
            if (dp < bnd) {
                float dfull = fmaxf(dp + q2, 0.f);
                unsigned cur = (__float_as_uint(dfull) & 0xFFFFF800u)
                             | (unsigned)(c + i);
#pragma unroll
                for (int j = 0; j < 16; j++) {
                    unsigned mn = min(bk[j], cur);
                    unsigned mx = max(bk[j], cur);
                    bk[j] = mn; cur = mx;
                }
                bnd = __uint_as_float(bk[15] & 0xFFFFF800u) - q2;
            }
        }
    }

    float w[16]; int ci[16]; float wsum = 0.f;
#pragma unroll
    for (int k = 0; k < 16; k++) {
        int c = (int)(bk[k] & 0x7FFu); ci[k] = c;
        float4 v = sp[c];
        float dx = qx - v.x, dy = qy - v.y, dz = qz - v.z;
        float d2 = fmaf(dx, dx, fmaf(dy, dy, dz * dz)) + 1e-16f;
        w[k] = 1.0f / d2; wsum += w[k];
    }
    float inv = 1.0f / wsum;
#pragma unroll
    for (int k = 0; k < 16; k++) {
        s_w[tid * 16 + k] = w[k] * inv;
        s_i[tid * 16 + k] = ci[k];
    }
    __syncwarp();

    int lane = tid & 31;
    int wbase2 = tid & ~31;
    for (int s = 0; s < 32; s++) {
        int t = wbase2 + s;
        int qq = __shfl_sync(0xFFFFFFFFu, q, s);
        float a0 = 0.f, a1 = 0.f;
#pragma unroll
        for (int k = 0; k < 16; k++) {
            int cix = s_i[t * 16 + k];
            float wk = s_w[t * 16 + k];
            const float* row = cc + cix * 64;
            a0 = fmaf(wk, row[lane], a0);
            a1 = fmaf(wk, row[lane + 32], a1);
        }
        g_X[(size_t)qq * 128 + lane] = to_tf32(a0);
        g_X[(size_t)qq * 128 + 32 + lane] = to_tf32(a1);
    }
}

// ===================== fused MLP: tf32 mma.sync ============================
// Warp grid 4x2 (w_r rows, w_c cols). Warp tile 32x64 (or 32x32 for dir).
// m16n8k8 fragments: a0=[g][t] a1=[g+8][t] a2=[g][t+4] a3=[g+8][t+4];
//                    b0=[k=t][n=g] b1=[k=t+4][n=g]; c=[g][2t],[g][2t+1],...
#define SMEM_FLOATS (128 * ASM + 32 * WSM + 128 + 192)

// 4 K-tiles of a 128-col layer. afull: A cols = tile*32..; stageX: stage X
// chunks into A[:,0:32] per tile (A offset 0).
__device__ __forceinline__ void run128(const float* __restrict__ Wg,
        float acc[2][8][4], float* A, float* Wb,
        int tid, int w_r, int w_c, int g, int t,
        bool stageX, const float* __restrict__ xsrc) {
    int sc4 = (tid & 31) * 4;
    int sk  = (tid >> 5) * 4;
    for (int tt = 0; tt < 4; tt++) {
        __syncthreads();
#pragma unroll
        for (int i = 0; i < 4; i++) {
            float4 v = *reinterpret_cast<const float4*>(
                Wg + (size_t)(tt * 32 + sk + i) * 128 + sc4);
            *reinterpret_cast<float4*>(Wb + (sk + i) * WSM + sc4) = v;
        }
        if (stageX) {
#pragma unroll
            for (int i = 0; i < 4; i++) {
                int row = (tid >> 3) + i * 32;
                int c4 = (tid & 7) * 4;
                float4 v = *reinterpret_cast<const float4*>(
                    xsrc + (size_t)row * 128 + tt * 32 + c4);
                *reinterpret_cast<float4*>(A + row * ASM + c4) = v;
            }
        }
        __syncthreads();
        int abase = stageX ? 0 : tt * 32;
#pragma unroll
        for (int k8 = 0; k8 < 4; k8++) {
            int ak = abase + k8 * 8;
            int r0 = w_r * 32 + g;
            float a0[4], a1[4];
            a0[0] = A[r0 * ASM + ak + t];
            a0[1] = A[(r0 + 8) * ASM + ak + t];
            a0[2] = A[r0 * ASM + ak + t + 4];
            a0[3] = A[(r0 + 8) * ASM + ak + t + 4];
            a1[0] = A[(r0 + 16) * ASM + ak + t];
            a1[1] = A[(r0 + 24) * ASM + ak + t];
            a1[2] = A[(r0 + 16) * ASM + ak + t + 4];
            a1[3] = A[(r0 + 24) * ASM + ak + t + 4];
            int kw = k8 * 8;
#pragma unroll
            for (int j = 0; j < 8; j++) {
                int cb = w_c * 64 + j * 8 + g;
                float b0 = Wb[(kw + t) * WSM + cb];
                float b1 = Wb[(kw + t + 4) * WSM + cb];
                mma8(acc[0][j], a0, b0, b1);
                mma8(acc[1][j], a1, b0, b1);
            }
        }
    }
}

__device__ __forceinline__ void ep128(float acc[2][8][4],
        const float* __restrict__ bias, bool relu,
        float* A, int w_r, int w_c, int g, int t) {
    __syncthreads();    // all mma reads of A done before overwrite
#pragma unroll
    for (int m = 0; m < 2; m++) {
        int r0 = w_r * 32 + m * 16 + g;
#pragma unroll
        for (int j = 0; j < 8; j++) {
            int C = w_c * 64 + j * 8 + 2 * t;
            float bv0 = bias[C], bv1 = bias[C + 1];
            float v0 = acc[m][j][0] + bv0, v1 = acc[m][j][1] + bv1;
            float v2 = acc[m][j][2] + bv0, v3 = acc[m][j][3] + bv1;
            if (relu) {
                v0 = fmaxf(v0, 0.f); v1 = fmaxf(v1, 0.f);
                v2 = fmaxf(v2, 0.f); v3 = fmaxf(v3, 0.f);
            }
            v0 = to_tf32(v0); v1 = to_tf32(v1);
            v2 = to_tf32(v2); v3 = to_tf32(v3);
            *reinterpret_cast<float2*>(A + r0 * ASM + C) = make_float2(v0, v1);
            *reinterpret_cast<float2*>(A + (r0 + 8) * ASM + C) = make_float2(v2, v3);
        }
    }
    __syncthreads();
}

__global__ void __launch_bounds__(256, 2) fused_mlp(
    const float* __restrict__ b0, const float* __restrict__ b1,
    const float* __restrict__ b2, const float* __restrict__ b3,
    const float* __restrict__ bf,
    const float* __restrict__ Wsig, const float* __restrict__ bs,
    const float* __restrict__ Wr,   const float* __restrict__ br,
    float* __restrict__ out)
{
    extern __shared__ float sm[];
    float* A   = sm;                    // 128 x ASM
    float* Wb  = sm + 128 * ASM;        // 32 x WSM
    float* wsv = Wb + 32 * WSM;
    float* wrv = wsv + 128;

    int tid = threadIdx.x;
    int lane = tid & 31, wid = tid >> 5;
    int w_r = wid & 3, w_c = wid >> 2;
    int g = lane >> 2, t = lane & 3;
    int rowBlk = blockIdx.x * 128;
    const float* xsrc = g_X + (size_t)rowBlk * 128;

    if (tid < 128) wsv[tid] = Wsig[tid];
    if (tid < 192) wrv[tid] = Wr[tid];

    // stage X block into A
    {
        const float4* src = reinterpret_cast<const float4*>(xsrc);
#pragma unroll
        for (int i = 0; i < 16; i++) {
            int f4 = tid + i * 256;
            float4 v = src[f4];
            int row = f4 >> 5, c4 = f4 & 31;
            *reinterpret_cast<float4*>(A + row * ASM + c4 * 4) = v;
        }
    }

    float acc[2][8][4];
    float sigR = 0.f;

#define CLR() do { _Pragma("unroll") for (int _m = 0; _m < 2; _m++) \
    _Pragma("unroll") for (int _j = 0; _j < 8; _j++) \
    _Pragma("unroll") for (int _i = 0; _i < 4; _i++) acc[_m][_j][_i] = 0.f; } while (0)

    // L0: h = relu(X @ W0 + b0)
    CLR();
    run128(g_W0p, acc, A, Wb, tid, w_r, w_c, g, t, false, xsrc);
    ep128(acc, b0, true, A, w_r, w_c, g, t);

    // L1: h = relu(h @ W1 + b1)
    CLR();
    run128(g_W1p, acc, A, Wb, tid, w_r, w_c, g, t, false, xsrc);
    ep128(acc, b1, true, A, w_r, w_c, g, t);

    // L2: h = relu(h @ W2h + X @ W2x + b2)   (skip folded, K=256)
    CLR();
    run128(g_W2hp, acc, A, Wb, tid, w_r, w_c, g, t, false, xsrc);
    run128(g_W2xp, acc, A, Wb, tid, w_r, w_c, g, t, true, xsrc);
    ep128(acc, b2, true, A, w_r, w_c, g, t);

    // L3: h = relu(h @ W3 + b3)
    CLR();
    run128(g_W3p, acc, A, Wb, tid, w_r, w_c, g, t, false, xsrc);
    ep128(acc, b3, true, A, w_r, w_c, g, t);

    // sigma = h @ Ws + bs  (h in A)
    if (tid < 128) {
        float s = 0.f;
#pragma unroll
        for (int k4 = 0; k4 < 32; k4++) {
            float4 hv = *reinterpret_cast<const float4*>(A + tid * ASM + k4 * 4);
            s = fmaf(hv.x, wsv[k4 * 4 + 0], s);
            s = fmaf(hv.y, wsv[k4 * 4 + 1], s);
            s = fmaf(hv.z, wsv[k4 * 4 + 2], s);
            s = fmaf(hv.w, wsv[k4 * 4 + 3], s);
        }
        sigR = s + bs[0];
    }

    // L4: final = h @ Wf + bf   (no relu)
    CLR();
    run128(g_Wfp, acc, A, Wb, tid, w_r, w_c, g, t, false, xsrc);
    ep128(acc, bf, false, A, w_r, w_c, g, t);

    // dir layer: d = relu(final @ Wdf + V), 64 cols
    CLR();
    {
        int sc4 = (tid & 15) * 4;
        int sk  = (tid >> 4) * 2;
        for (int tt = 0; tt < 4; tt++) {
            __syncthreads();
#pragma unroll
            for (int i = 0; i < 2; i++) {
                float4 v = *reinterpret_cast<const float4*>(
                    g_Wdfp + (size_t)(tt * 32 + sk + i) * 64 + sc4);
                *reinterpret_cast<float4*>(Wb + (sk + i) * WSM + sc4) = v;
            }
            __syncthreads();
#pragma unroll
            for (int k8 = 0; k8 < 4; k8++) {
                int ak = tt * 32 + k8 * 8;
                int r0 = w_r * 32 + g;
                float a0[4], a1[4];
                a0[0] = A[r0 * ASM + ak + t];
                a0[1] = A[(r0 + 8) * ASM + ak + t];
                a0[2] = A[r0 * ASM + ak + t + 4];
                a0[3] = A[(r0 + 8) * ASM + ak + t + 4];
                a1[0] = A[(r0 + 16) * ASM + ak + t];
                a1[1] = A[(r0 + 24) * ASM + ak + t];
                a1[2] = A[(r0 + 16) * ASM + ak + t + 4];
                a1[3] = A[(r0 + 24) * ASM + ak + t + 4];
                int kw = k8 * 8;
#pragma unroll
                for (int j = 0; j < 4; j++) {
                    int cb = w_c * 32 + j * 8 + g;
                    float b0 = Wb[(kw + t) * WSM + cb];
                    float b1 = Wb[(kw + t + 4) * WSM + cb];
                    mma8(acc[0][j], a0, b0, b1);
                    mma8(acc[1][j], a1, b0, b1);
                }
            }
        }
    }
    // dir epilogue: +V, relu, store to A cols 0..63 (fp32, feeds scalar rgb)
    __syncthreads();
#pragma unroll
    for (int m = 0; m < 2; m++) {
        int r0 = w_r * 32 + m * 16 + g;
#pragma unroll
        for (int j = 0; j < 4; j++) {
            int C = w_c * 32 + j * 8 + 2 * t;
            float2 va = *reinterpret_cast<const float2*>(
                g_V + (size_t)(rowBlk + r0) * 64 + C);
            float2 vb = *reinterpret_cast<const float2*>(
                g_V + (size_t)(rowBlk + r0 + 8) * 64 + C);
            float v0 = fmaxf(acc[m][j][0] + va.x, 0.f);
            float v1 = fmaxf(acc[m][j][1] + va.y, 0.f);
            float v2 = fmaxf(acc[m][j][2] + vb.x, 0.f);
            float v3 = fmaxf(acc[m][j][3] + vb.y, 0.f);
            *reinterpret_cast<float2*>(A + r0 * ASM + C) = make_float2(v0, v1);
            *reinterpret_cast<float2*>(A + (r0 + 8) * ASM + C) = make_float2(v2, v3);
        }
    }
    __syncthreads();

    // rgb + output
    if (tid < 128) {
        float r0 = br[0], r1 = br[1], r2 = br[2];
#pragma unroll
        for (int k4 = 0; k4 < 16; k4++) {
            float4 dv = *reinterpret_cast<const float4*>(A + tid * ASM + k4 * 4);
            const float* wr0 = wrv + k4 * 12;
            r0 = fmaf(dv.x, wr0[0], r0); r1 = fmaf(dv.x, wr0[1], r1); r2 = fmaf(dv.x, wr0[2], r2);
            r0 = fmaf(dv.y, wr0[3], r0); r1 = fmaf(dv.y, wr0[4], r1); r2 = fmaf(dv.y, wr0[5], r2);
            r0 = fmaf(dv.z, wr0[6], r0); r1 = fmaf(dv.z, wr0[7], r1); r2 = fmaf(dv.z, wr0[8], r2);
            r0 = fmaf(dv.w, wr0[9], r0); r1 = fmaf(dv.w, wr0[10], r1); r2 = fmaf(dv.w, wr0[11], r2);
        }
        *reinterpret_cast<float4*>(out + (size_t)(rowBlk + tid) * 4) =
            make_float4(r0, r1, r2, sigR);
    }
}

// ---------------------------------------------------------------------------
extern "C" void kernel_launch(void* const* d_in, const int* in_sizes, int n_in,
                              void* d_out, int out_size) {
    const int*   indices = (const int*)  d_in[0];
    const float* qp      = (const float*)d_in[1];
    const float* xyzdir  = (const float*)d_in[2];
    const float* cpos    = (const float*)d_in[3];
    const float* codes   = (const float*)d_in[4];
    const float* W0 = (const float*)d_in[5],  *b0 = (const float*)d_in[6];
    const float* W1 = (const float*)d_in[7],  *b1 = (const float*)d_in[8];
    const float* W2 = (const float*)d_in[9],  *b2 = (const float*)d_in[10];
    const float* W3 = (const float*)d_in[11], *b3 = (const float*)d_in[12];
    const float* Wf = (const float*)d_in[13], *bf = (const float*)d_in[14];
    const float* Wd = (const float*)d_in[15], *bd = (const float*)d_in[16];
    const float* Ws = (const float*)d_in[17], *bs = (const float*)d_in[18];
    const float* Wr = (const float*)d_in[19], *br = (const float*)d_in[20];
    float* out = (float*)d_out;

    const int smemBytes = SMEM_FLOATS * 4;
    cudaFuncSetAttribute(fused_mlp, cudaFuncAttributeMaxDynamicSharedMemorySize,
                         smemBytes);

    void* histPtr = nullptr;
    cudaGetSymbolAddress(&histPtr, g_hist);
    cudaMemsetAsync(histPtr, 0, 4096 * sizeof(int));

    hist_k<<<NQ / 256, 256>>>(qp);
    prologue_k<<<5344, 256>>>(W0, W1, W2, W3, Wf, Wd, bd, xyzdir);
    scan_k<<<1, 1024>>>();
    scatter_k<<<NQ / 256, 256>>>(qp);
    knn_interp<<<NQ / 128, 128>>>(indices, qp, cpos, codes);
    fused_mlp<<<NQ / 128, 256, smemBytes>>>(b0, b1, b2, b3, bf,
                                            Ws, bs, Wr, br, out);
}

// round 13
// speedup vs baseline: 2.2472x; 1.0557x over previous
#include <cuda_runtime.h>
#include <cstdint>

#define NQ 65536
#define NC 2048
#define ASM 132   // activation smem row stride (floats), 132 % 32 == 4
#define WSM 136   // weight-tile smem row stride (floats), 136 % 32 == 8

// ------- device scratch (static __device__ globals: allocation-free) -------
__device__ float g_X[NQ * 128];    // tf32-rounded [query_codes 64 | xyz 63 | 0]
__device__ float g_V[NQ * 64];     // dir @ Wd_dir + bd  (fp32)
__device__ int   g_hist[4096];
__device__ int   g_offs[4096];
__device__ int   g_perm[NQ];
__device__ float g_W0p[128 * 128]; // all weights tf32-rounded, padded
__device__ float g_W1p[128 * 128];
__device__ float g_W2xp[128 * 128];
__device__ float g_W2hp[128 * 128];
__device__ float g_W3p[128 * 128];
__device__ float g_Wfp[128 * 128];
__device__ float g_Wdfp[128 * 64];

// ------------------------- helpers -----------------------------------------
__device__ __forceinline__ float to_tf32(float x) {
    float r; asm("cvt.rna.tf32.f32 %0, %1;" : "=f"(r) : "f"(x)); return r;
}
__device__ __forceinline__ void mma8(float* c, const float* a, float b0, float b1) {
    asm volatile(
        "mma.sync.aligned.m16n8k8.row.col.f32.tf32.tf32.f32 "
        "{%0,%1,%2,%3}, {%4,%5,%6,%7}, {%8,%9}, {%0,%1,%2,%3};"
        : "+f"(c[0]), "+f"(c[1]), "+f"(c[2]), "+f"(c[3])
        : "r"(__float_as_uint(a[0])), "r"(__float_as_uint(a[1])),
          "r"(__float_as_uint(a[2])), "r"(__float_as_uint(a[3])),
          "r"(__float_as_uint(b0)), "r"(__float_as_uint(b1)));
}
__device__ __forceinline__ int cell_of(float x, float y, float z) {
    int ix = min(15, max(0, (int)(x * 16.f)));
    int iy = min(15, max(0, (int)(y * 16.f)));
    int iz = min(15, max(0, (int)(z * 16.f)));
    return (ix << 8) | (iy << 4) | iz;
}

// --------------------- spatial counting sort of queries --------------------
__global__ void hist_k(const float* __restrict__ qp) {
    int q = blockIdx.x * 256 + threadIdx.x;
    atomicAdd(&g_hist[cell_of(qp[3 * q], qp[3 * q + 1], qp[3 * q + 2])], 1);
}

__global__ void __launch_bounds__(1024) scan_k() {   // 1 block
    __shared__ int s[1024];
    int tid = threadIdx.x;
    int v[4]; int sum = 0;
#pragma unroll
    for (int i = 0; i < 4; i++) { v[i] = g_hist[tid * 4 + i]; sum += v[i]; }
    s[tid] = sum; __syncthreads();
    for (int off = 1; off < 1024; off <<= 1) {
        int t = (tid >= off) ? s[tid - off] : 0;
        __syncthreads();
        s[tid] += t;
        __syncthreads();
    }
    int run = tid ? s[tid - 1] : 0;
#pragma unroll
    for (int i = 0; i < 4; i++) { g_offs[tid * 4 + i] = run; run += v[i]; }
}

__global__ void scatter_k(const float* __restrict__ qp) {
    int q = blockIdx.x * 256 + threadIdx.x;
    int cell = cell_of(qp[3 * q], qp[3 * q + 1], qp[3 * q + 2]);
    int pos = atomicAdd(&g_offs[cell], 1);
    g_perm[pos] = q;
}

// ------ merged prologue: weight prep (tf32) | xyz pack | V comp ------------
__global__ void __launch_bounds__(256) prologue_k(
        const float* __restrict__ W0, const float* __restrict__ W1,
        const float* __restrict__ W2, const float* __restrict__ W3,
        const float* __restrict__ Wf, const float* __restrict__ Wd,
        const float* __restrict__ bd, const float* __restrict__ xyzdir) {
    int bid = blockIdx.x;
    int tid = threadIdx.x;
    const int T = 16384;
    if (bid < 224) {
        int total = 6 * T + 8192;
        for (int i = bid * 256 + tid; i < total; i += 224 * 256) {
            if (i < T) {
                int r = i >> 7, c = i & 127;
                g_W0p[i] = (r < 127) ? to_tf32(W0[r * 128 + c]) : 0.f;
            } else if (i < 2 * T) {
                int j = i - T;
                g_W1p[j] = to_tf32(W1[j]);
            } else if (i < 3 * T) {
                int j = i - 2 * T; int r = j >> 7, c = j & 127;
                g_W2xp[j] = (r < 127) ? to_tf32(W2[r * 128 + c]) : 0.f;
            } else if (i < 4 * T) {
                int j = i - 3 * T; int r = j >> 7, c = j & 127;
                g_W2hp[j] = to_tf32(W2[(127 + r) * 128 + c]);
            } else if (i < 5 * T) {
                int j = i - 4 * T;
                g_W3p[j] = to_tf32(W3[j]);
            } else if (i < 6 * T) {
                int j = i - 5 * T;
                g_Wfp[j] = to_tf32(Wf[j]);
            } else {
                int j = i - 6 * T;
                g_Wdfp[j] = to_tf32(Wd[j]);
            }
        }
    } else if (bid < 1248) {
        const int total = NQ * 64;
        for (int i = (bid - 224) * 256 + tid; i < total; i += 1024 * 256) {
            int q = i >> 6, e = i & 63;
            g_X[q * 128 + 64 + e] = (e < 63) ? to_tf32(xyzdir[q * 90 + e]) : 0.f;
        }
    } else {
        __shared__ float sw[27 * 64];
        __shared__ float sb[64];
        for (int i = tid; i < 27 * 64; i += 256) sw[i] = Wd[128 * 64 + i];
        if (tid < 64) sb[tid] = bd[tid];
        __syncthreads();
        int idx = (bid - 1248) * 256 + tid;     // NQ*16 threads
        int q = idx >> 4, c0 = (idx & 15) * 4;
        float a0 = sb[c0], a1 = sb[c0 + 1], a2 = sb[c0 + 2], a3 = sb[c0 + 3];
        const float* dirp = xyzdir + (size_t)q * 90 + 63;
#pragma unroll
        for (int k = 0; k < 27; k++) {
            float dv = dirp[k];
            a0 = fmaf(dv, sw[k * 64 + c0 + 0], a0);
            a1 = fmaf(dv, sw[k * 64 + c0 + 1], a1);
            a2 = fmaf(dv, sw[k * 64 + c0 + 2], a2);
            a3 = fmaf(dv, sw[k * 64 + c0 + 3], a3);
        }
        *reinterpret_cast<float4*>(g_V + (size_t)q * 64 + c0) =
            make_float4(a0, a1, a2, a3);
    }
}

// --------- KNN(16) + interpolation, fused; clustered queries ---------------
// Inner loop: 4-wide min pre-check -> one compare/branch per 4 candidates.
__global__ void __launch_bounds__(128) knn_interp(const int* __restrict__ indices,
                                                  const float* __restrict__ qp,
                                                  const float* __restrict__ cpos,
                                                  const float* __restrict__ codes) {
    __shared__ float4 sp[NC];      // {x, y, z, ||c||^2}
    __shared__ float s_w[128 * 16];
    __shared__ int   s_i[128 * 16];
    int tid = threadIdx.x;
    int ib = indices[0];
    const float* cp = cpos + (size_t)ib * NC * 3;
    const float* cc = codes + (size_t)ib * NC * 64;
    for (int c = tid; c < NC; c += 128) {
        float x = cp[c * 3 + 0], y = cp[c * 3 + 1], z = cp[c * 3 + 2];
        sp[c] = make_float4(x, y, z, fmaf(x, x, fmaf(y, y, z * z)));
    }
    __syncthreads();

    int q = g_perm[blockIdx.x * 128 + tid];
    float qx = qp[q * 3 + 0], qy = qp[q * 3 + 1], qz = qp[q * 3 + 2];
    float qx2 = -2.f * qx, qy2 = -2.f * qy, qz2 = -2.f * qz;
    float q2 = fmaf(qx, qx, fmaf(qy, qy, qz * qz));

    unsigned bk[16];
#pragma unroll
    for (int j = 0; j < 16; j++) bk[j] = 0x7F7FFFFFu;
    float bnd = __uint_as_float(0x7F7FF800u) - q2;

    for (int c = 0; c < NC; c += 4) {
        float dp[4];
#pragma unroll
        for (int i = 0; i < 4; i++) {
            float4 v = sp[c + i];
            dp[i] = fmaf(v.x, qx2, fmaf(v.y, qy2, fmaf(v.z, qz2, v.w)));
        }
        float mn4 = fminf(fminf(dp[0], dp[1]), fminf(dp[2], dp[3]));
        if (mn4 < bnd) {
#pragma unroll
            for (int i = 0; i < 4; i++) {
                if (dp[i] < bnd) {
                    float dfull = fmaxf(dp[i] + q2, 0.f);
                    unsigned cur = (__float_as_uint(dfull) & 0xFFFFF800u)
                                 | (unsigned)(c + i);
#pragma unroll
                    for (int j = 0; j < 16; j++) {
                        unsigned lo = min(bk[j], cur);
                        unsigned hi = max(bk[j], cur);
                        bk[j] = lo; cur = hi;
                    }
                    bnd = __uint_as_float(bk[15] & 0xFFFFF800u) - q2;
                }
            }
        }
    }

    float w[16]; int ci[16]; float wsum = 0.f;
#pragma unroll
    for (int k = 0; k < 16; k++) {
        int c = (int)(bk[k] & 0x7FFu); ci[k] = c;
        float4 v = sp[c];
        float dx = qx - v.x, dy = qy - v.y, dz = qz - v.z;
        float d2 = fmaf(dx, dx, fmaf(dy, dy, dz * dz)) + 1e-16f;
        w[k] = 1.0f / d2; wsum += w[k];
    }
    float inv = 1.0f / wsum;
#pragma unroll
    for (int k = 0; k < 16; k++) {
        s_w[tid * 16 + k] = w[k] * inv;
        s_i[tid * 16 + k] = ci[k];
    }
    __syncwarp();

    int lane = tid & 31;
    int wbase2 = tid & ~31;
    for (int s = 0; s < 32; s++) {
        int t = wbase2 + s;
        int qq = __shfl_sync(0xFFFFFFFFu, q, s);
        float a0 = 0.f, a1 = 0.f;
#pragma unroll
        for (int k = 0; k < 16; k++) {
            int cix = s_i[t * 16 + k];
            float wk = s_w[t * 16 + k];
            const float* row = cc + cix * 64;
            a0 = fmaf(wk, row[lane], a0);
            a1 = fmaf(wk, row[lane + 32], a1);
        }
        g_X[(size_t)qq * 128 + lane] = to_tf32(a0);
        g_X[(size_t)qq * 128 + 32 + lane] = to_tf32(a1);
    }
}

// ===================== fused MLP: tf32 mma.sync ============================
// Warp grid 4x2. Warp tile 32x64 (32x32 dir). Double-buffered weight tiles.
#define SMEM_FLOATS (128 * ASM + 2 * 32 * WSM + 128 + 192)

__device__ __forceinline__ void mma_tile(float acc[2][8][4], const float* A,
        const float* Wt, int abase, int w_r, int w_c, int g, int t) {
#pragma unroll
    for (int k8 = 0; k8 < 4; k8++) {
        int ak = abase + k8 * 8;
        int r0 = w_r * 32 + g;
        float a0[4], a1[4];
        a0[0] = A[r0 * ASM + ak + t];
        a0[1] = A[(r0 + 8) * ASM + ak + t];
        a0[2] = A[r0 * ASM + ak + t + 4];
        a0[3] = A[(r0 + 8) * ASM + ak + t + 4];
        a1[0] = A[(r0 + 16) * ASM + ak + t];
        a1[1] = A[(r0 + 24) * ASM + ak + t];
        a1[2] = A[(r0 + 16) * ASM + ak + t + 4];
        a1[3] = A[(r0 + 24) * ASM + ak + t + 4];
        int kw = k8 * 8;
#pragma unroll
        for (int j = 0; j < 8; j++) {
            int cb = w_c * 64 + j * 8 + g;
            float b0 = Wt[(kw + t) * WSM + cb];
            float b1 = Wt[(kw + t + 4) * WSM + cb];
            mma8(acc[0][j], a0, b0, b1);
            mma8(acc[1][j], a1, b0, b1);
        }
    }
}

// double-buffered 4-tile pass (A stays fixed)
__device__ __forceinline__ void run128_db(const float* __restrict__ Wg,
        float acc[2][8][4], const float* A, float* Wb,
        int tid, int w_r, int w_c, int g, int t) {
    int sc4 = (tid & 31) * 4;
    int sk  = (tid >> 5) * 4;
    float4 pf[4];
#pragma unroll
    for (int i = 0; i < 4; i++)
        pf[i] = *reinterpret_cast<const float4*>(Wg + (size_t)(sk + i) * 128 + sc4);
#pragma unroll
    for (int i = 0; i < 4; i++)
        *reinterpret_cast<float4*>(Wb + (sk + i) * WSM + sc4) = pf[i];
    __syncthreads();
    for (int tt = 0; tt < 4; tt++) {
        if (tt < 3) {
#pragma unroll
            for (int i = 0; i < 4; i++)
                pf[i] = *reinterpret_cast<const float4*>(
                    Wg + (size_t)((tt + 1) * 32 + sk + i) * 128 + sc4);
        }
        mma_tile(acc, A, Wb + (tt & 1) * (32 * WSM), tt * 32, w_r, w_c, g, t);
        if (tt < 3) {
            float* d = Wb + ((tt + 1) & 1) * (32 * WSM);
#pragma unroll
            for (int i = 0; i < 4; i++)
                *reinterpret_cast<float4*>(d + (sk + i) * WSM + sc4) = pf[i];
        }
        __syncthreads();
    }
}

// stageX variant: stages X chunks into A[:,0:32] per tile (conservative syncs)
__device__ __forceinline__ void run128_sx(const float* __restrict__ Wg,
        float acc[2][8][4], float* A, float* Wb,
        int tid, int w_r, int w_c, int g, int t,
        const float* __restrict__ xsrc) {
    int sc4 = (tid & 31) * 4;
    int sk  = (tid >> 5) * 4;
    for (int tt = 0; tt < 4; tt++) {
        __syncthreads();
#pragma unroll
        for (int i = 0; i < 4; i++) {
            float4 v = *reinterpret_cast<const float4*>(
                Wg + (size_t)(tt * 32 + sk + i) * 128 + sc4);
            *reinterpret_cast<float4*>(Wb + (sk + i) * WSM + sc4) = v;
        }
#pragma unroll
        for (int i = 0; i < 4; i++) {
            int row = (tid >> 3) + i * 32;
            int c4 = (tid & 7) * 4;
            float4 v = *reinterpret_cast<const float4*>(
                xsrc + (size_t)row * 128 + tt * 32 + c4);
            *reinterpret_cast<float4*>(A + row * ASM + c4) = v;
        }
        __syncthreads();
        mma_tile(acc, A, Wb, 0, w_r, w_c, g, t);
    }
    __syncthreads();
}

__device__ __forceinline__ void ep128(float acc[2][8][4],
        const float* __restrict__ bias, bool relu,
        float* A, int w_r, int w_c, int g, int t) {
    __syncthreads();
#pragma unroll
    for (int m = 0; m < 2; m++) {
        int r0 = w_r * 32 + m * 16 + g;
#pragma unroll
        for (int j = 0; j < 8; j++) {
            int C = w_c * 64 + j * 8 + 2 * t;
            float bv0 = bias[C], bv1 = bias[C + 1];
            float v0 = acc[m][j][0] + bv0, v1 = acc[m][j][1] + bv1;
            float v2 = acc[m][j][2] + bv0, v3 = acc[m][j][3] + bv1;
            if (relu) {
                v0 = fmaxf(v0, 0.f); v1 = fmaxf(v1, 0.f);
                v2 = fmaxf(v2, 0.f); v3 = fmaxf(v3, 0.f);
            }
            v0 = to_tf32(v0); v1 = to_tf32(v1);
            v2 = to_tf32(v2); v3 = to_tf32(v3);
            *reinterpret_cast<float2*>(A + r0 * ASM + C) = make_float2(v0, v1);
            *reinterpret_cast<float2*>(A + (r0 + 8) * ASM + C) = make_float2(v2, v3);
        }
    }
    __syncthreads();
}

__global__ void __launch_bounds__(256, 2) fused_mlp(
    const float* __restrict__ b0, const float* __restrict__ b1,
    const float* __restrict__ b2, const float* __restrict__ b3,
    const float* __restrict__ bf,
    const float* __restrict__ Wsig, const float* __restrict__ bs,
    const float* __restrict__ Wr,   const float* __restrict__ br,
    float* __restrict__ out)
{
    extern __shared__ float sm[];
    float* A   = sm;                    // 128 x ASM
    float* Wb  = sm + 128 * ASM;        // 2 x 32 x WSM
    float* wsv = Wb + 2 * 32 * WSM;
    float* wrv = wsv + 128;

    int tid = threadIdx.x;
    int lane = tid & 31, wid = tid >> 5;
    int w_r = wid & 3, w_c = wid >> 2;
    int g = lane >> 2, t = lane & 3;
    int rowBlk = blockIdx.x * 128;
    const float* xsrc = g_X + (size_t)rowBlk * 128;

    if (tid < 128) wsv[tid] = Wsig[tid];
    if (tid < 192) wrv[tid] = Wr[tid];

    {
        const float4* src = reinterpret_cast<const float4*>(xsrc);
#pragma unroll
        for (int i = 0; i < 16; i++) {
            int f4 = tid + i * 256;
            float4 v = src[f4];
            int row = f4 >> 5, c4 = f4 & 31;
            *reinterpret_cast<float4*>(A + row * ASM + c4 * 4) = v;
        }
    }
    __syncthreads();

    float acc[2][8][4];
    float sigR = 0.f;

#define CLR() do { _Pragma("unroll") for (int _m = 0; _m < 2; _m++) \
    _Pragma("unroll") for (int _j = 0; _j < 8; _j++) \
    _Pragma("unroll") for (int _i = 0; _i < 4; _i++) acc[_m][_j][_i] = 0.f; } while (0)

    CLR();
    run128_db(g_W0p, acc, A, Wb, tid, w_r, w_c, g, t);
    ep128(acc, b0, true, A, w_r, w_c, g, t);

    CLR();
    run128_db(g_W1p, acc, A, Wb, tid, w_r, w_c, g, t);
    ep128(acc, b1, true, A, w_r, w_c, g, t);

    // L2: skip folded, K=256
    CLR();
    run128_db(g_W2hp, acc, A, Wb, tid, w_r, w_c, g, t);
    run128_sx(g_W2xp, acc, A, Wb, tid, w_r, w_c, g, t, xsrc);
    ep128(acc, b2, true, A, w_r, w_c, g, t);

    CLR();
    run128_db(g_W3p, acc, A, Wb, tid, w_r, w_c, g, t);
    ep128(acc, b3, true, A, w_r, w_c, g, t);

    // sigma = h @ Ws + bs
    if (tid < 128) {
        float s = 0.f;
#pragma unroll
        for (int k4 = 0; k4 < 32; k4++) {
            float4 hv = *reinterpret_cast<const float4*>(A + tid * ASM + k4 * 4);
            s = fmaf(hv.x, wsv[k4 * 4 + 0], s);
            s = fmaf(hv.y, wsv[k4 * 4 + 1], s);
            s = fmaf(hv.z, wsv[k4 * 4 + 2], s);
            s = fmaf(hv.w, wsv[k4 * 4 + 3], s);
        }
        sigR = s + bs[0];
    }

    CLR();
    run128_db(g_Wfp, acc, A, Wb, tid, w_r, w_c, g, t);
    ep128(acc, bf, false, A, w_r, w_c, g, t);

    // dir layer: d = relu(final @ Wdf + V), 64 cols
    CLR();
    {
        int sc4 = (tid & 15) * 4;
        int sk  = (tid >> 4) * 2;
        for (int tt = 0; tt < 4; tt++) {
            __syncthreads();
#pragma unroll
            for (int i = 0; i < 2; i++) {
                float4 v = *reinterpret_cast<const float4*>(
                    g_Wdfp + (size_t)(tt * 32 + sk + i) * 64 + sc4);
                *reinterpret_cast<float4*>(Wb + (sk + i) * WSM + sc4) = v;
            }
            __syncthreads();
#pragma unroll
            for (int k8 = 0; k8 < 4; k8++) {
                int ak = tt * 32 + k8 * 8;
                int r0 = w_r * 32 + g;
                float a0[4], a1[4];
                a0[0] = A[r0 * ASM + ak + t];
                a0[1] = A[(r0 + 8) * ASM + ak + t];
                a0[2] = A[r0 * ASM + ak + t + 4];
                a0[3] = A[(r0 + 8) * ASM + ak + t + 4];
                a1[0] = A[(r0 + 16) * ASM + ak + t];
                a1[1] = A[(r0 + 24) * ASM + ak + t];
                a1[2] = A[(r0 + 16) * ASM + ak + t + 4];
                a1[3] = A[(r0 + 24) * ASM + ak + t + 4];
                int kw = k8 * 8;
#pragma unroll
                for (int j = 0; j < 4; j++) {
                    int cb = w_c * 32 + j * 8 + g;
                    float b0 = Wb[(kw + t) * WSM + cb];
                    float b1 = Wb[(kw + t + 4) * WSM + cb];
                    mma8(acc[0][j], a0, b0, b1);
                    mma8(acc[1][j], a1, b0, b1);
                }
            }
        }
    }
    __syncthreads();
#pragma unroll
    for (int m = 0; m < 2; m++) {
        int r0 = w_r * 32 + m * 16 + g;
#pragma unroll
        for (int j = 0; j < 4; j++) {
            int C = w_c * 32 + j * 8 + 2 * t;
            float2 va = *reinterpret_cast<const float2*>(
                g_V + (size_t)(rowBlk + r0) * 64 + C);
            float2 vb = *reinterpret_cast<const float2*>(
                g_V + (size_t)(rowBlk + r0 + 8) * 64 + C);
            float v0 = fmaxf(acc[m][j][0] + va.x, 0.f);
            float v1 = fmaxf(acc[m][j][1] + va.y, 0.f);
            float v2 = fmaxf(acc[m][j][2] + vb.x, 0.f);
            float v3 = fmaxf(acc[m][j][3] + vb.y, 0.f);
            *reinterpret_cast<float2*>(A + r0 * ASM + C) = make_float2(v0, v1);
            *reinterpret_cast<float2*>(A + (r0 + 8) * ASM + C) = make_float2(v2, v3);
        }
    }
    __syncthreads();

    // rgb + output
    if (tid < 128) {
        float r0 = br[0], r1 = br[1], r2 = br[2];
#pragma unroll
        for (int k4 = 0; k4 < 16; k4++) {
            float4 dv = *reinterpret_cast<const float4*>(A + tid * ASM + k4 * 4);
            const float* wr0 = wrv + k4 * 12;
            r0 = fmaf(dv.x, wr0[0], r0); r1 = fmaf(dv.x, wr0[1], r1); r2 = fmaf(dv.x, wr0[2], r2);
            r0 = fmaf(dv.y, wr0[3], r0); r1 = fmaf(dv.y, wr0[4], r1); r2 = fmaf(dv.y, wr0[5], r2);
            r0 = fmaf(dv.z, wr0[6], r0); r1 = fmaf(dv.z, wr0[7], r1); r2 = fmaf(dv.z, wr0[8], r2);
            r0 = fmaf(dv.w, wr0[9], r0); r1 = fmaf(dv.w, wr0[10], r1); r2 = fmaf(dv.w, wr0[11], r2);
        }
        *reinterpret_cast<float4*>(out + (size_t)(rowBlk + tid) * 4) =
            make_float4(r0, r1, r2, sigR);
    }
}

// ---------------------------------------------------------------------------
extern "C" void kernel_launch(void* const* d_in, const int* in_sizes, int n_in,
                              void* d_out, int out_size) {
    const int*   indices = (const int*)  d_in[0];
    const float* qp      = (const float*)d_in[1];
    const float* xyzdir  = (const float*)d_in[2];
    const float* cpos    = (const float*)d_in[3];
    const float* codes   = (const float*)d_in[4];
    const float* W0 = (const float*)d_in[5],  *b0 = (const float*)d_in[6];
    const float* W1 = (const float*)d_in[7],  *b1 = (const float*)d_in[8];
    const float* W2 = (const float*)d_in[9],  *b2 = (const float*)d_in[10];
    const float* W3 = (const float*)d_in[11], *b3 = (const float*)d_in[12];
    const float* Wf = (const float*)d_in[13], *bf = (const float*)d_in[14];
    const float* Wd = (const float*)d_in[15], *bd = (const float*)d_in[16];
    const float* Ws = (const float*)d_in[17], *bs = (const float*)d_in[18];
    const float* Wr = (const float*)d_in[19], *br = (const float*)d_in[20];
    float* out = (float*)d_out;

    const int smemBytes = SMEM_FLOATS * 4;
    cudaFuncSetAttribute(fused_mlp, cudaFuncAttributeMaxDynamicSharedMemorySize,
                         smemBytes);

    void* histPtr = nullptr;
    cudaGetSymbolAddress(&histPtr, g_hist);
    cudaMemsetAsync(histPtr, 0, 4096 * sizeof(int));

    hist_k<<<NQ / 256, 256>>>(qp);
    prologue_k<<<5344, 256>>>(W0, W1, W2, W3, Wf, Wd, bd, xyzdir);
    scan_k<<<1, 1024>>>();
    scatter_k<<<NQ / 256, 256>>>(qp);
    knn_interp<<<NQ / 128, 128>>>(indices, qp, cpos, codes);
    fused_mlp<<<NQ / 128, 256, smemBytes>>>(b0, b1, b2, b3, bf,
                                            Ws, bs, Wr, br, out);
}